// round 14
// baseline (speedup 1.0000x reference)
#include <cuda_runtime.h>
#include <cuda_fp16.h>
#include <cstdint>
#include <math.h>

// ---------------- problem constants ----------------
#define N_PTS 32768
#define D_DIM 512
#define M_FEAT 512
#define KEPS 0.001f
#define NSTAB 1e-6f
#define KV_SPLIT 16
#define QK_YB (N_PTS / 64)      // 512 row-blocks for colsum partials

// ---------------- scratch ----------------
__device__ __half g_xh[(size_t)N_PTS * D_DIM];
__device__ __half g_chih[(size_t)N_PTS * D_DIM];
__device__ __half g_Bqh[M_FEAT * D_DIM];
__device__ __half g_Bkh[M_FEAT * D_DIM];
__device__ float g_cq[M_FEAT];
__device__ float g_ck[M_FEAT];
__device__ __half g_qph[(size_t)N_PTS * M_FEAT];
__device__ __half g_kph[(size_t)N_PTS * M_FEAT];
__device__ float g_ks_part[QK_YB * M_FEAT];
__device__ float g_ks[M_FEAT];
__device__ float g_kvpart[(size_t)KV_SPLIT * D_DIM * M_FEAT];
__device__ __half g_kvh[D_DIM * M_FEAT];

// ---------------- helpers ----------------
__device__ __forceinline__ uint32_t smem_u32(const void* p) {
    uint32_t a;
    asm("{ .reg .u64 t; cvta.to.shared.u64 t, %1; cvt.u32.u64 %0, t; }" : "=r"(a) : "l"(p));
    return a;
}
__device__ __forceinline__ void cp_async16(uint32_t saddr, const void* gptr) {
    asm volatile("cp.async.cg.shared.global [%0], [%1], 16;" :: "r"(saddr), "l"(gptr) : "memory");
}
__device__ __forceinline__ void cp_commit() { asm volatile("cp.async.commit_group;" ::: "memory"); }
template<int N>
__device__ __forceinline__ void cp_wait() { asm volatile("cp.async.wait_group %0;" :: "n"(N) : "memory"); }

__device__ __forceinline__ void mma_f16(float* c, const uint32_t* a, const uint32_t* b) {
    asm volatile(
        "mma.sync.aligned.m16n8k16.row.col.f32.f16.f16.f32 "
        "{%0,%1,%2,%3}, {%4,%5,%6,%7}, {%8,%9}, {%0,%1,%2,%3};"
        : "+f"(c[0]), "+f"(c[1]), "+f"(c[2]), "+f"(c[3])
        : "r"(a[0]), "r"(a[1]), "r"(a[2]), "r"(a[3]), "r"(b[0]), "r"(b[1]));
}
__device__ __forceinline__ void ldsm_x4(uint32_t& r0, uint32_t& r1, uint32_t& r2, uint32_t& r3,
                                        uint32_t addr) {
    asm volatile("ldmatrix.sync.aligned.m8n8.x4.shared.b16 {%0,%1,%2,%3}, [%4];"
                 : "=r"(r0), "=r"(r1), "=r"(r2), "=r"(r3) : "r"(addr));
}
__device__ __forceinline__ void ldsm_x4_t(uint32_t& r0, uint32_t& r1, uint32_t& r2, uint32_t& r3,
                                          uint32_t addr) {
    asm volatile("ldmatrix.sync.aligned.m8n8.x4.trans.shared.b16 {%0,%1,%2,%3}, [%4];"
                 : "=r"(r0), "=r"(r1), "=r"(r2), "=r"(r3) : "r"(addr));
}

// ============ NT fp16 GEMM: 64m x 128n tile, 8 warps (2m x 4n), warp 32x32 ============
#define LQH 40                          // smem row stride in halves (32 data + 8 pad)
#define A_STG_H (64 * LQH)
#define B_STG_H (128 * LQH)
#define A_STG_B (A_STG_H * 2)           // 5120 B
#define B_STG_B (B_STG_H * 2)           // 10240 B
#define NT_SMEM (4 * (A_STG_B + B_STG_B))   // 61440 B

// ---------------- qk: q'/k' = relu(x @ B^T + c) + eps ----------------
__global__ void __launch_bounds__(256, 3) k_gemm_qk() {
    extern __shared__ __align__(16) char smraw[];
    __half* Asm = (__half*)smraw;                       // 4 stages A
    __half* Bsm = (__half*)(smraw + 4 * A_STG_B);       // 4 stages B
    __shared__ float scol[2][128];

    const int tid = threadIdx.x;
    const int wid = tid >> 5, lane = tid & 31;
    const int wr = wid & 1, wc = wid >> 1;      // 2 m-warps x 4 n-warps
    const int mW = wr * 32, nW = wc * 32;
    const int rowBase = blockIdx.y * 64;
    const int colBase = blockIdx.x * 128;
    const bool isK = (blockIdx.z == 1);
    const __half* Bg = isK ? g_Bkh : g_Bqh;
    const float* ev = isK ? g_ck : g_cq;

    const uint32_t aB = smem_u32(Asm), bB = smem_u32(Bsm);

    auto stage = [&](int buf, int kb) {
        {   // A: 64 rows x 32 halves = 256 chunks, 1 per thread
            const int row = tid >> 2;
            const int ch = (tid & 3) * 8;
            cp_async16(aB + buf * A_STG_B + (row * LQH + ch) * 2,
                       g_xh + (size_t)(rowBase + row) * D_DIM + kb + ch);
        }
#pragma unroll
        for (int i = 0; i < 2; i++) {   // B: 128 rows x 32 halves = 512 chunks
            const int c = tid + i * 256;
            const int row = c >> 2;
            const int ch = (c & 3) * 8;
            cp_async16(bB + buf * B_STG_B + (row * LQH + ch) * 2,
                       Bg + (size_t)(colBase + row) * D_DIM + kb + ch);
        }
        cp_commit();
    };

    float acc[2][4][4];
#pragma unroll
    for (int mt = 0; mt < 2; mt++)
#pragma unroll
        for (int nt = 0; nt < 4; nt++)
#pragma unroll
            for (int j = 0; j < 4; j++) acc[mt][nt][j] = 0.f;

    const int nk = D_DIM / 32;   // 16
    stage(0, 0); stage(1, 32); stage(2, 64);
    const int rr = lane >> 2, cc = lane & 3;
    const int lrow = lane & 15, lsel = (lane >> 4) << 3;

    const uint32_t aBase = aB + ((mW + lrow) * LQH + lsel) * 2;
    const uint32_t bBase = bB + ((nW + lrow) * LQH + lsel) * 2;

#pragma unroll 4
    for (int kt = 0; kt < nk; kt++) {
        cp_wait<2>();
        __syncthreads();
        if (kt + 3 < nk) stage((kt + 3) & 3, (kt + 3) * 32);
        const uint32_t soA = (uint32_t)(kt & 3) * A_STG_B;
        const uint32_t soB = (uint32_t)(kt & 3) * B_STG_B;
#pragma unroll
        for (int ks = 0; ks < 2; ks++) {
            const uint32_t ko = ks * 32;          // 16 halves
            uint32_t a[2][4], b[4][2];
#pragma unroll
            for (int mt = 0; mt < 2; mt++)
                ldsm_x4(a[mt][0], a[mt][1], a[mt][2], a[mt][3],
                        aBase + soA + ko + mt * (16 * LQH * 2));
#pragma unroll
            for (int p = 0; p < 2; p++) {
                uint32_t r0, r1, r2, r3;
                ldsm_x4(r0, r1, r2, r3, bBase + soB + ko + p * (16 * LQH * 2));
                b[2 * p][0] = r0; b[2 * p][1] = r2;
                b[2 * p + 1][0] = r1; b[2 * p + 1][1] = r3;
            }
#pragma unroll
            for (int mt = 0; mt < 2; mt++)
#pragma unroll
                for (int nt = 0; nt < 4; nt++)
                    mma_f16(acc[mt][nt], a[mt], b[nt]);
        }
    }

    if (!isK) {
#pragma unroll
        for (int mt = 0; mt < 2; mt++)
#pragma unroll
            for (int hf = 0; hf < 2; hf++) {
                const int r = rowBase + mW + mt * 16 + rr + hf * 8;
#pragma unroll
                for (int nt = 0; nt < 4; nt++) {
                    const int c0 = colBase + nW + nt * 8 + 2 * cc;
                    float v0 = fmaxf(acc[mt][nt][hf * 2] + ev[c0], 0.f) + KEPS;
                    float v1 = fmaxf(acc[mt][nt][hf * 2 + 1] + ev[c0 + 1], 0.f) + KEPS;
                    *(half2*)(g_qph + (size_t)r * M_FEAT + c0) = __floats2half2_rn(v0, v1);
                }
            }
    } else {
        float cs[4][2];
#pragma unroll
        for (int nt = 0; nt < 4; nt++) { cs[nt][0] = 0.f; cs[nt][1] = 0.f; }
#pragma unroll
        for (int mt = 0; mt < 2; mt++)
#pragma unroll
            for (int hf = 0; hf < 2; hf++) {
                const int r = rowBase + mW + mt * 16 + rr + hf * 8;
#pragma unroll
                for (int nt = 0; nt < 4; nt++) {
                    const int c0 = colBase + nW + nt * 8 + 2 * cc;
                    float v0 = fmaxf(acc[mt][nt][hf * 2] + ev[c0], 0.f) + KEPS;
                    float v1 = fmaxf(acc[mt][nt][hf * 2 + 1] + ev[c0 + 1], 0.f) + KEPS;
                    *(half2*)(g_kph + (size_t)r * M_FEAT + c0) = __floats2half2_rn(v0, v1);
                    cs[nt][0] += v0; cs[nt][1] += v1;
                }
            }
        // reduce over rr within warp (lanes xor 4,8,16)
#pragma unroll
        for (int nt = 0; nt < 4; nt++)
#pragma unroll
            for (int j = 0; j < 2; j++) {
                float s = cs[nt][j];
                s += __shfl_xor_sync(0xffffffffu, s, 4);
                s += __shfl_xor_sync(0xffffffffu, s, 8);
                s += __shfl_xor_sync(0xffffffffu, s, 16);
                cs[nt][j] = s;
            }
        if (rr == 0) {
#pragma unroll
            for (int nt = 0; nt < 4; nt++) {
                scol[wr][nW + nt * 8 + 2 * cc] = cs[nt][0];
                scol[wr][nW + nt * 8 + 2 * cc + 1] = cs[nt][1];
            }
        }
        __syncthreads();
        if (tid < 128)
            g_ks_part[blockIdx.y * M_FEAT + colBase + tid] = scol[0][tid] + scol[1][tid];
    }
}

// ---------------- num: out = (qph @ kvh^T) * 1/den, den fused ----------------
__global__ void __launch_bounds__(256, 3) k_gemm_num(float* __restrict__ out) {
    extern __shared__ __align__(16) char smraw[];
    __half* Asm = (__half*)smraw;
    __half* Bsm = (__half*)(smraw + 4 * A_STG_B);
    __shared__ float kss[512];

    const int tid = threadIdx.x;
    const int wid = tid >> 5, lane = tid & 31;
    const int wr = wid & 1, wc = wid >> 1;
    const int mW = wr * 32, nW = wc * 32;
    const int rowBase = blockIdx.y * 64;
    const int colBase = blockIdx.x * 128;

    kss[tid] = g_ks[tid];
    kss[tid + 256] = g_ks[tid + 256];

    const uint32_t aB = smem_u32(Asm), bB = smem_u32(Bsm);

    auto stage = [&](int buf, int kb) {
        {
            const int row = tid >> 2;
            const int ch = (tid & 3) * 8;
            cp_async16(aB + buf * A_STG_B + (row * LQH + ch) * 2,
                       g_qph + (size_t)(rowBase + row) * M_FEAT + kb + ch);
        }
#pragma unroll
        for (int i = 0; i < 2; i++) {
            const int c = tid + i * 256;
            const int row = c >> 2;
            const int ch = (c & 3) * 8;
            cp_async16(bB + buf * B_STG_B + (row * LQH + ch) * 2,
                       g_kvh + (size_t)(colBase + row) * M_FEAT + kb + ch);
        }
        cp_commit();
    };

    float acc[2][4][4];
#pragma unroll
    for (int mt = 0; mt < 2; mt++)
#pragma unroll
        for (int nt = 0; nt < 4; nt++)
#pragma unroll
            for (int j = 0; j < 4; j++) acc[mt][nt][j] = 0.f;
    float den[2][2] = {{0.f, 0.f}, {0.f, 0.f}};

    const int nk = M_FEAT / 32;  // 16
    stage(0, 0); stage(1, 32); stage(2, 64);
    const int rr = lane >> 2, cc = lane & 3;
    const int lrow = lane & 15, lsel = (lane >> 4) << 3;

    const uint32_t aBase = aB + ((mW + lrow) * LQH + lsel) * 2;
    const uint32_t bBase = bB + ((nW + lrow) * LQH + lsel) * 2;

#pragma unroll 4
    for (int kt = 0; kt < nk; kt++) {
        cp_wait<2>();
        __syncthreads();
        if (kt + 3 < nk) stage((kt + 3) & 3, (kt + 3) * 32);
        const uint32_t soA = (uint32_t)(kt & 3) * A_STG_B;
        const uint32_t soB = (uint32_t)(kt & 3) * B_STG_B;
#pragma unroll
        for (int ks = 0; ks < 2; ks++) {
            const uint32_t ko = ks * 32;
            uint32_t a[2][4], b[4][2];
#pragma unroll
            for (int mt = 0; mt < 2; mt++)
                ldsm_x4(a[mt][0], a[mt][1], a[mt][2], a[mt][3],
                        aBase + soA + ko + mt * (16 * LQH * 2));
#pragma unroll
            for (int p = 0; p < 2; p++) {
                uint32_t r0, r1, r2, r3;
                ldsm_x4(r0, r1, r2, r3, bBase + soB + ko + p * (16 * LQH * 2));
                b[2 * p][0] = r0; b[2 * p][1] = r2;
                b[2 * p + 1][0] = r1; b[2 * p + 1][1] = r3;
            }
            const int kbase = kt * 32 + ks * 16;
            const float2 kA = *(const float2*)&kss[kbase + 2 * cc];
            const float2 kB = *(const float2*)&kss[kbase + 8 + 2 * cc];
#pragma unroll
            for (int mt = 0; mt < 2; mt++) {
                float2 a0 = __half22float2(*(const half2*)&a[mt][0]);
                float2 a1 = __half22float2(*(const half2*)&a[mt][1]);
                float2 a2 = __half22float2(*(const half2*)&a[mt][2]);
                float2 a3 = __half22float2(*(const half2*)&a[mt][3]);
                den[mt][0] += a0.x * kA.x + a0.y * kA.y + a2.x * kB.x + a2.y * kB.y;
                den[mt][1] += a1.x * kA.x + a1.y * kA.y + a3.x * kB.x + a3.y * kB.y;
            }
#pragma unroll
            for (int mt = 0; mt < 2; mt++)
#pragma unroll
                for (int nt = 0; nt < 4; nt++)
                    mma_f16(acc[mt][nt], a[mt], b[nt]);
        }
    }

    float inv[2][2];
#pragma unroll
    for (int mt = 0; mt < 2; mt++)
#pragma unroll
        for (int h = 0; h < 2; h++) {
            float d = den[mt][h];
            d += __shfl_xor_sync(0xffffffffu, d, 1);
            d += __shfl_xor_sync(0xffffffffu, d, 2);
            if (fabsf(d) <= NSTAB) d += 2.f * NSTAB;
            inv[mt][h] = 1.f / d;
        }

#pragma unroll
    for (int mt = 0; mt < 2; mt++)
#pragma unroll
        for (int hf = 0; hf < 2; hf++) {
            const int r = rowBase + mW + mt * 16 + rr + hf * 8;
            const float sc = inv[mt][hf];
#pragma unroll
            for (int nt = 0; nt < 4; nt++) {
                const int c0 = colBase + nW + nt * 8 + 2 * cc;
                *(float2*)(out + (size_t)r * D_DIM + c0) =
                    make_float2(acc[mt][nt][hf * 2] * sc, acc[mt][nt][hf * 2 + 1] * sc);
            }
        }
}

// ========== kv TT fp16 GEMM (R8 version): kvT[d,m] = sum_n chih[n,d]*kph[n,m] ==========
#define LKV 136
#define KV_STG_H (32 * LKV)
#define KV_STG_B (KV_STG_H * 2)
#define KV_SMEM (3 * 2 * KV_STG_B)

__global__ void __launch_bounds__(256, 2) k_gemm_kv() {
    extern __shared__ __align__(16) char smraw[];
    __half* Asm = (__half*)smraw;
    __half* Bsm = Asm + 3 * KV_STG_H;

    const int tid = threadIdx.x;
    const int wid = tid >> 5, lane = tid & 31;
    const int wr = wid & 3, wc = wid >> 2;
    const int mW = wr * 32, nW = wc * 64;
    const int rowBase = blockIdx.y * 128;   // d
    const int colBase = blockIdx.x * 128;   // m
    const int kBeg = blockIdx.z * (N_PTS / KV_SPLIT);
    float* C = g_kvpart + (size_t)blockIdx.z * D_DIM * M_FEAT;

    const uint32_t aB = smem_u32(Asm), bB = smem_u32(Bsm);

    auto stage = [&](int buf, int kb) {
#pragma unroll
        for (int i = 0; i < 2; i++) {
            const int c = tid + i * 256;
            const int row = c >> 4;
            const int ch = (c & 15) * 8;
            cp_async16(aB + buf * KV_STG_B + (row * LKV + ch) * 2,
                       g_chih + (size_t)(kb + row) * D_DIM + rowBase + ch);
            cp_async16(bB + buf * KV_STG_B + (row * LKV + ch) * 2,
                       g_kph + (size_t)(kb + row) * M_FEAT + colBase + ch);
        }
        cp_commit();
    };

    float acc[2][8][4];
#pragma unroll
    for (int mt = 0; mt < 2; mt++)
#pragma unroll
        for (int nt = 0; nt < 8; nt++)
#pragma unroll
            for (int j = 0; j < 4; j++) acc[mt][nt][j] = 0.f;

    const int nk = (N_PTS / KV_SPLIT) / 32;      // 64
    stage(0, kBeg);
    stage(1, kBeg + 32);
    const int rr = lane >> 2, cc = lane & 3;
    const int lrow = lane & 15, lsel = (lane >> 4) << 3;

    const uint32_t aBase = aB + (lrow * LKV + mW + lsel) * 2;
    const uint32_t bBase = bB + (lrow * LKV + nW + lsel) * 2;

    uint32_t soff = 0;
    for (int kt = 0; kt < nk; kt++) {
        cp_wait<1>();
        __syncthreads();
        if (kt + 2 < nk) stage((kt + 2) % 3, kBeg + (kt + 2) * 32);
#pragma unroll
        for (int ks = 0; ks < 2; ks++) {
            const uint32_t ko = soff + ks * (16 * LKV * 2);
            uint32_t a[2][4], b[8][2];
#pragma unroll
            for (int mt = 0; mt < 2; mt++) {
                uint32_t r0, r1, r2, r3;
                ldsm_x4_t(r0, r1, r2, r3, aBase + ko + mt * 32);
                a[mt][0] = r0; a[mt][1] = r2; a[mt][2] = r1; a[mt][3] = r3;
            }
#pragma unroll
            for (int p = 0; p < 4; p++) {
                uint32_t r0, r1, r2, r3;
                ldsm_x4_t(r0, r1, r2, r3, bBase + ko + p * 32);
                b[2 * p][0] = r0; b[2 * p][1] = r1;
                b[2 * p + 1][0] = r2; b[2 * p + 1][1] = r3;
            }
#pragma unroll
            for (int mt = 0; mt < 2; mt++)
#pragma unroll
                for (int nt = 0; nt < 8; nt++)
                    mma_f16(acc[mt][nt], a[mt], b[nt]);
        }
        soff += KV_STG_B;
        if (soff == 3 * KV_STG_B) soff = 0;
    }

#pragma unroll
    for (int mt = 0; mt < 2; mt++)
#pragma unroll
        for (int hf = 0; hf < 2; hf++) {
            const int r = rowBase + mW + mt * 16 + rr + hf * 8;
#pragma unroll
            for (int nt = 0; nt < 8; nt++) {
                const int c0 = colBase + nW + nt * 8 + 2 * cc;
                *(float2*)(C + (size_t)r * M_FEAT + c0) =
                    make_float2(acc[mt][nt][hf * 2], acc[mt][nt][hf * 2 + 1]);
            }
        }
}

// ---------------- prep GEMM: Bq/Bk = proj @ W^T -> fp16 ----------------
#define BM 128
#define BN 128
#define BK 8
__global__ void __launch_bounds__(256) k_prep(const float* __restrict__ proj,
                                              const float* __restrict__ Wq,
                                              const float* __restrict__ Wk) {
    const float* B = blockIdx.z ? Wk : Wq;
    __half* C = blockIdx.z ? g_Bkh : g_Bqh;
    __shared__ float As[BK][BM];
    __shared__ float Bs[BK][BN];
    const int tid = threadIdx.x;
    const int tx = tid & 15, ty = tid >> 4;
    const int rowBase = blockIdx.y * BM, colBase = blockIdx.x * BN;
    const int rA = tid >> 1, cA = (tid & 1) * 4;

    float acc[8][8];
#pragma unroll
    for (int i = 0; i < 8; i++)
#pragma unroll
        for (int j = 0; j < 8; j++) acc[i][j] = 0.f;

    for (int kb = 0; kb < D_DIM; kb += BK) {
        float4 av = *(const float4*)(proj + (rowBase + rA) * D_DIM + kb + cA);
        float4 bv = *(const float4*)(B + (colBase + rA) * D_DIM + kb + cA);
        __syncthreads();
        As[cA + 0][rA] = av.x; As[cA + 1][rA] = av.y; As[cA + 2][rA] = av.z; As[cA + 3][rA] = av.w;
        Bs[cA + 0][rA] = bv.x; Bs[cA + 1][rA] = bv.y; Bs[cA + 2][rA] = bv.z; Bs[cA + 3][rA] = bv.w;
        __syncthreads();
#pragma unroll
        for (int k = 0; k < BK; k++) {
            float a[8], b[8];
#pragma unroll
            for (int i = 0; i < 8; i++) a[i] = As[k][ty * 8 + i];
#pragma unroll
            for (int j = 0; j < 8; j++) b[j] = Bs[k][tx * 8 + j];
#pragma unroll
            for (int i = 0; i < 8; i++)
#pragma unroll
                for (int j = 0; j < 8; j++) acc[i][j] = fmaf(a[i], b[j], acc[i][j]);
        }
    }
#pragma unroll
    for (int i = 0; i < 8; i++) {
        __half* cp = C + (rowBase + ty * 8 + i) * D_DIM + colBase + tx * 8;
#pragma unroll
        for (int j = 0; j < 8; j++) cp[j] = __float2half_rn(acc[i][j]);
    }
}

__global__ void k_bias(const float* __restrict__ bq, const float* __restrict__ bk,
                       const float* __restrict__ proj) {
    int m = blockIdx.x * blockDim.x + threadIdx.x;
    const float* b = blockIdx.y ? bk : bq;
    float* c = blockIdx.y ? g_ck : g_cq;
    float s = 0.f;
    for (int j = 0; j < D_DIM; j++) s += b[j] * proj[m * D_DIM + j];
    c[m] = s;
}

// x -> g_xh (z=0), chi -> g_chih (z=1)
__global__ void k_cvt(const float* __restrict__ x, const float* __restrict__ chi) {
    const float* src = blockIdx.z ? chi : x;
    __half* dst = blockIdx.z ? g_chih : g_xh;
    size_t i = ((size_t)blockIdx.x * 256 + threadIdx.x) * 8;
    float4 v0 = *(const float4*)(src + i);
    float4 v1 = *(const float4*)(src + i + 4);
    half2 h0 = __floats2half2_rn(v0.x, v0.y);
    half2 h1 = __floats2half2_rn(v0.z, v0.w);
    half2 h2 = __floats2half2_rn(v1.x, v1.y);
    half2 h3 = __floats2half2_rn(v1.z, v1.w);
    uint4 o = make_uint4(*(uint32_t*)&h0, *(uint32_t*)&h1, *(uint32_t*)&h2, *(uint32_t*)&h3);
    *(uint4*)(dst + i) = o;
}

// ks[m] = sum over 512 row-block partials
__global__ void k_colsum2() {
    int m = blockIdx.x * 32 + threadIdx.x;
    float s = 0.f;
    for (int y = 0; y < QK_YB; y++) s += g_ks_part[y * M_FEAT + m];
    g_ks[m] = s;
}

__global__ void k_kvred() {
    int i = blockIdx.x * blockDim.x + threadIdx.x;
    float s = 0.f;
#pragma unroll
    for (int z = 0; z < KV_SPLIT; z++) s += g_kvpart[(size_t)z * D_DIM * M_FEAT + i];
    g_kvh[i] = __float2half_rn(s);
}

// ---------------- launch ----------------
extern "C" void kernel_launch(void* const* d_in, const int* in_sizes, int n_in,
                              void* d_out, int out_size) {
    const float* chi  = (const float*)d_in[0];
    const float* x    = (const float*)d_in[1];
    const float* Wq   = (const float*)d_in[2];
    const float* bq   = (const float*)d_in[3];
    const float* Wk   = (const float*)d_in[4];
    const float* bk   = (const float*)d_in[5];
    const float* proj = (const float*)d_in[6];
    float* out = (float*)d_out;

    cudaFuncSetAttribute(k_gemm_qk,  cudaFuncAttributeMaxDynamicSharedMemorySize, NT_SMEM);
    cudaFuncSetAttribute(k_gemm_num, cudaFuncAttributeMaxDynamicSharedMemorySize, NT_SMEM);
    cudaFuncSetAttribute(k_gemm_kv,  cudaFuncAttributeMaxDynamicSharedMemorySize, KV_SMEM);

    k_prep<<<dim3(D_DIM / BN, M_FEAT / BM, 2), 256>>>(proj, Wq, Wk);
    k_bias<<<dim3(2, 2), 256>>>(bq, bk, proj);
    k_cvt<<<dim3((N_PTS * D_DIM) / (256 * 8), 1, 2), 256>>>(x, chi);
    // qk: 64-row x 128-col tiles, 3 CTAs/SM
    k_gemm_qk<<<dim3(M_FEAT / 128, N_PTS / 64, 2), 256, NT_SMEM>>>();
    k_colsum2<<<16, 32>>>();
    k_gemm_kv<<<dim3(M_FEAT / 128, D_DIM / 128, KV_SPLIT), 256, KV_SMEM>>>();
    k_kvred<<<(D_DIM * M_FEAT) / 256, 256>>>();
    k_gemm_num<<<dim3(D_DIM / 128, N_PTS / 64), 256, NT_SMEM>>>(out);
}

// round 15
// speedup vs baseline: 1.1039x; 1.1039x over previous
#include <cuda_runtime.h>
#include <cuda_fp16.h>
#include <cstdint>
#include <math.h>

// ---------------- problem constants ----------------
#define N_PTS 32768
#define D_DIM 512
#define M_FEAT 512
#define KEPS 0.001f
#define NSTAB 1e-6f
#define KV_SPLIT 16
#define QK_YB (N_PTS / 128)     // 256

// ---------------- scratch ----------------
__device__ __half g_xh[(size_t)N_PTS * D_DIM];
__device__ __half g_chih[(size_t)N_PTS * D_DIM];
__device__ __half g_Bqh[M_FEAT * D_DIM];
__device__ __half g_Bkh[M_FEAT * D_DIM];
__device__ float g_cq[M_FEAT];
__device__ float g_ck[M_FEAT];
__device__ __half g_qph[(size_t)N_PTS * M_FEAT];
__device__ __half g_kph[(size_t)N_PTS * M_FEAT];
__device__ float g_ks_part[QK_YB * M_FEAT];
__device__ float g_ks[M_FEAT];
__device__ float g_kvpart[(size_t)KV_SPLIT * D_DIM * M_FEAT];
__device__ __half g_kvh[D_DIM * M_FEAT];

// ---------------- helpers ----------------
__device__ __forceinline__ uint32_t smem_u32(const void* p) {
    uint32_t a;
    asm("{ .reg .u64 t; cvta.to.shared.u64 t, %1; cvt.u32.u64 %0, t; }" : "=r"(a) : "l"(p));
    return a;
}
__device__ __forceinline__ void cp_async16(uint32_t saddr, const void* gptr) {
    asm volatile("cp.async.cg.shared.global [%0], [%1], 16;" :: "r"(saddr), "l"(gptr) : "memory");
}
__device__ __forceinline__ void cp_commit() { asm volatile("cp.async.commit_group;" ::: "memory"); }
template<int N>
__device__ __forceinline__ void cp_wait() { asm volatile("cp.async.wait_group %0;" :: "n"(N) : "memory"); }

__device__ __forceinline__ void mma_f16(float* c, const uint32_t* a, const uint32_t* b) {
    asm volatile(
        "mma.sync.aligned.m16n8k16.row.col.f32.f16.f16.f32 "
        "{%0,%1,%2,%3}, {%4,%5,%6,%7}, {%8,%9}, {%0,%1,%2,%3};"
        : "+f"(c[0]), "+f"(c[1]), "+f"(c[2]), "+f"(c[3])
        : "r"(a[0]), "r"(a[1]), "r"(a[2]), "r"(a[3]), "r"(b[0]), "r"(b[1]));
}
__device__ __forceinline__ void ldsm_x4(uint32_t& r0, uint32_t& r1, uint32_t& r2, uint32_t& r3,
                                        uint32_t addr) {
    asm volatile("ldmatrix.sync.aligned.m8n8.x4.shared.b16 {%0,%1,%2,%3}, [%4];"
                 : "=r"(r0), "=r"(r1), "=r"(r2), "=r"(r3) : "r"(addr));
}
__device__ __forceinline__ void ldsm_x4_t(uint32_t& r0, uint32_t& r1, uint32_t& r2, uint32_t& r3,
                                          uint32_t addr) {
    asm volatile("ldmatrix.sync.aligned.m8n8.x4.trans.shared.b16 {%0,%1,%2,%3}, [%4];"
                 : "=r"(r0), "=r"(r1), "=r"(r2), "=r"(r3) : "r"(addr));
}

// ======= NT fp16 GEMM: 128x128 tile, 8 warps (4m x 2n), BK=64, 3 stages =======
#define LQH 72                        // 64 data + 8 pad halves
#define NT_STG_H (128 * LQH)
#define NT_STG_B (NT_STG_H * 2)       // 18432 B per operand-stage
#define NT_SMEM (3 * 2 * NT_STG_B)    // 110592 B

// ---------------- qk: q'/k' = relu(x @ B^T + c) + eps ----------------
__global__ void __launch_bounds__(256, 2) k_gemm_qk() {
    extern __shared__ __align__(16) char smraw[];
    __half* Asm = (__half*)smraw;                     // 3 stages A
    __half* Bsm = (__half*)(smraw + 3 * NT_STG_B);    // 3 stages B
    __shared__ float scol[4][128];

    const int tid = threadIdx.x;
    const int wid = tid >> 5, lane = tid & 31;
    const int wr = wid & 3, wc = wid >> 2;
    const int mW = wr * 32, nW = wc * 64;
    const int rowBase = blockIdx.y * 128;
    const int colBase = blockIdx.x * 128;
    const bool isK = (blockIdx.z == 1);
    const __half* Bg = isK ? g_Bkh : g_Bqh;
    const float* ev = isK ? g_ck : g_cq;

    const uint32_t aB = smem_u32(Asm), bB = smem_u32(Bsm);

    auto stage = [&](uint32_t so, int kb) {
#pragma unroll
        for (int i = 0; i < 4; i++) {          // 128 rows x 64 halves per operand
            const int c = tid + i * 256;
            const int row = c >> 3;
            const int ch = (c & 7) * 8;
            cp_async16(aB + so + (row * LQH + ch) * 2,
                       g_xh + (size_t)(rowBase + row) * D_DIM + kb + ch);
            cp_async16(bB + so + (row * LQH + ch) * 2,
                       Bg + (size_t)(colBase + row) * D_DIM + kb + ch);
        }
        cp_commit();
    };

    float acc[2][8][4];
#pragma unroll
    for (int mt = 0; mt < 2; mt++)
#pragma unroll
        for (int nt = 0; nt < 8; nt++)
#pragma unroll
            for (int j = 0; j < 4; j++) acc[mt][nt][j] = 0.f;

    const int nk = D_DIM / 64;   // 8
    stage(0, 0); stage(NT_STG_B, 64);
    const int rr = lane >> 2, cc = lane & 3;
    const int lrow = lane & 15, lsel = (lane >> 4) << 3;

    const uint32_t aBase = aB + ((mW + lrow) * LQH + lsel) * 2;
    const uint32_t bBase = bB + ((nW + lrow) * LQH + lsel) * 2;

    uint32_t cso = 0, sso = 2 * NT_STG_B;
    for (int kt = 0; kt < nk; kt++) {
        cp_wait<1>();
        __syncthreads();
        if (kt + 2 < nk) {
            stage(sso, (kt + 2) * 64);
            sso += NT_STG_B; if (sso == 3 * NT_STG_B) sso = 0;
        }
#pragma unroll
        for (int ks = 0; ks < 4; ks++) {
            const uint32_t ko = cso + ks * 32;      // 16 halves = 32 B
            uint32_t a[2][4], b[8][2];
#pragma unroll
            for (int mt = 0; mt < 2; mt++)
                ldsm_x4(a[mt][0], a[mt][1], a[mt][2], a[mt][3],
                        aBase + ko + mt * (16 * LQH * 2));
#pragma unroll
            for (int p = 0; p < 4; p++) {
                uint32_t r0, r1, r2, r3;
                ldsm_x4(r0, r1, r2, r3, bBase + ko + p * (16 * LQH * 2));
                b[2 * p][0] = r0; b[2 * p][1] = r2;
                b[2 * p + 1][0] = r1; b[2 * p + 1][1] = r3;
            }
#pragma unroll
            for (int mt = 0; mt < 2; mt++)
#pragma unroll
                for (int nt = 0; nt < 8; nt++)
                    mma_f16(acc[mt][nt], a[mt], b[nt]);
        }
        cso += NT_STG_B; if (cso == 3 * NT_STG_B) cso = 0;
    }

    if (!isK) {
#pragma unroll
        for (int mt = 0; mt < 2; mt++)
#pragma unroll
            for (int hf = 0; hf < 2; hf++) {
                const int r = rowBase + mW + mt * 16 + rr + hf * 8;
#pragma unroll
                for (int nt = 0; nt < 8; nt++) {
                    const int c0 = colBase + nW + nt * 8 + 2 * cc;
                    float v0 = fmaxf(acc[mt][nt][hf * 2] + ev[c0], 0.f) + KEPS;
                    float v1 = fmaxf(acc[mt][nt][hf * 2 + 1] + ev[c0 + 1], 0.f) + KEPS;
                    *(half2*)(g_qph + (size_t)r * M_FEAT + c0) = __floats2half2_rn(v0, v1);
                }
            }
    } else {
        float cs[8][2];
#pragma unroll
        for (int nt = 0; nt < 8; nt++) { cs[nt][0] = 0.f; cs[nt][1] = 0.f; }
#pragma unroll
        for (int mt = 0; mt < 2; mt++)
#pragma unroll
            for (int hf = 0; hf < 2; hf++) {
                const int r = rowBase + mW + mt * 16 + rr + hf * 8;
#pragma unroll
                for (int nt = 0; nt < 8; nt++) {
                    const int c0 = colBase + nW + nt * 8 + 2 * cc;
                    float v0 = fmaxf(acc[mt][nt][hf * 2] + ev[c0], 0.f) + KEPS;
                    float v1 = fmaxf(acc[mt][nt][hf * 2 + 1] + ev[c0 + 1], 0.f) + KEPS;
                    *(half2*)(g_kph + (size_t)r * M_FEAT + c0) = __floats2half2_rn(v0, v1);
                    cs[nt][0] += v0; cs[nt][1] += v1;
                }
            }
#pragma unroll
        for (int nt = 0; nt < 8; nt++)
#pragma unroll
            for (int j = 0; j < 2; j++) {
                float s = cs[nt][j];
                s += __shfl_xor_sync(0xffffffffu, s, 4);
                s += __shfl_xor_sync(0xffffffffu, s, 8);
                s += __shfl_xor_sync(0xffffffffu, s, 16);
                cs[nt][j] = s;
            }
        if (rr == 0) {
#pragma unroll
            for (int nt = 0; nt < 8; nt++) {
                scol[wr][nW + nt * 8 + 2 * cc] = cs[nt][0];
                scol[wr][nW + nt * 8 + 2 * cc + 1] = cs[nt][1];
            }
        }
        __syncthreads();
        if (tid < 128)
            g_ks_part[blockIdx.y * M_FEAT + colBase + tid] =
                scol[0][tid] + scol[1][tid] + scol[2][tid] + scol[3][tid];
    }
}

// ---------------- num: out = (qph @ kvh^T) * 1/den, den fused ----------------
__global__ void __launch_bounds__(256, 2) k_gemm_num(float* __restrict__ out) {
    extern __shared__ __align__(16) char smraw[];
    __half* Asm = (__half*)smraw;
    __half* Bsm = (__half*)(smraw + 3 * NT_STG_B);
    __shared__ float kss[512];

    const int tid = threadIdx.x;
    const int wid = tid >> 5, lane = tid & 31;
    const int wr = wid & 3, wc = wid >> 2;
    const int mW = wr * 32, nW = wc * 64;
    const int rowBase = blockIdx.y * 128;
    const int colBase = blockIdx.x * 128;

    kss[tid] = g_ks[tid];
    kss[tid + 256] = g_ks[tid + 256];

    const uint32_t aB = smem_u32(Asm), bB = smem_u32(Bsm);

    auto stage = [&](uint32_t so, int kb) {
#pragma unroll
        for (int i = 0; i < 4; i++) {
            const int c = tid + i * 256;
            const int row = c >> 3;
            const int ch = (c & 7) * 8;
            cp_async16(aB + so + (row * LQH + ch) * 2,
                       g_qph + (size_t)(rowBase + row) * M_FEAT + kb + ch);
            cp_async16(bB + so + (row * LQH + ch) * 2,
                       g_kvh + (size_t)(colBase + row) * M_FEAT + kb + ch);
        }
        cp_commit();
    };

    float acc[2][8][4];
#pragma unroll
    for (int mt = 0; mt < 2; mt++)
#pragma unroll
        for (int nt = 0; nt < 8; nt++)
#pragma unroll
            for (int j = 0; j < 4; j++) acc[mt][nt][j] = 0.f;
    float den[2][2] = {{0.f, 0.f}, {0.f, 0.f}};

    const int nk = M_FEAT / 64;  // 8
    stage(0, 0); stage(NT_STG_B, 64);
    const int rr = lane >> 2, cc = lane & 3;
    const int lrow = lane & 15, lsel = (lane >> 4) << 3;

    const uint32_t aBase = aB + ((mW + lrow) * LQH + lsel) * 2;
    const uint32_t bBase = bB + ((nW + lrow) * LQH + lsel) * 2;

    uint32_t cso = 0, sso = 2 * NT_STG_B;
    for (int kt = 0; kt < nk; kt++) {
        cp_wait<1>();
        __syncthreads();
        if (kt + 2 < nk) {
            stage(sso, (kt + 2) * 64);
            sso += NT_STG_B; if (sso == 3 * NT_STG_B) sso = 0;
        }
#pragma unroll
        for (int ks = 0; ks < 4; ks++) {
            const uint32_t ko = cso + ks * 32;
            uint32_t a[2][4], b[8][2];
#pragma unroll
            for (int mt = 0; mt < 2; mt++)
                ldsm_x4(a[mt][0], a[mt][1], a[mt][2], a[mt][3],
                        aBase + ko + mt * (16 * LQH * 2));
#pragma unroll
            for (int p = 0; p < 4; p++) {
                uint32_t r0, r1, r2, r3;
                ldsm_x4(r0, r1, r2, r3, bBase + ko + p * (16 * LQH * 2));
                b[2 * p][0] = r0; b[2 * p][1] = r2;
                b[2 * p + 1][0] = r1; b[2 * p + 1][1] = r3;
            }
            const int kbase = kt * 64 + ks * 16;
            const float2 kA = *(const float2*)&kss[kbase + 2 * cc];
            const float2 kB = *(const float2*)&kss[kbase + 8 + 2 * cc];
#pragma unroll
            for (int mt = 0; mt < 2; mt++) {
                float2 a0 = __half22float2(*(const half2*)&a[mt][0]);
                float2 a1 = __half22float2(*(const half2*)&a[mt][1]);
                float2 a2 = __half22float2(*(const half2*)&a[mt][2]);
                float2 a3 = __half22float2(*(const half2*)&a[mt][3]);
                den[mt][0] += a0.x * kA.x + a0.y * kA.y + a2.x * kB.x + a2.y * kB.y;
                den[mt][1] += a1.x * kA.x + a1.y * kA.y + a3.x * kB.x + a3.y * kB.y;
            }
#pragma unroll
            for (int mt = 0; mt < 2; mt++)
#pragma unroll
                for (int nt = 0; nt < 8; nt++)
                    mma_f16(acc[mt][nt], a[mt], b[nt]);
        }
        cso += NT_STG_B; if (cso == 3 * NT_STG_B) cso = 0;
    }

    float inv[2][2];
#pragma unroll
    for (int mt = 0; mt < 2; mt++)
#pragma unroll
        for (int h = 0; h < 2; h++) {
            float d = den[mt][h];
            d += __shfl_xor_sync(0xffffffffu, d, 1);
            d += __shfl_xor_sync(0xffffffffu, d, 2);
            if (fabsf(d) <= NSTAB) d += 2.f * NSTAB;
            inv[mt][h] = 1.f / d;
        }

#pragma unroll
    for (int mt = 0; mt < 2; mt++)
#pragma unroll
        for (int hf = 0; hf < 2; hf++) {
            const int r = rowBase + mW + mt * 16 + rr + hf * 8;
            const float sc = inv[mt][hf];
#pragma unroll
            for (int nt = 0; nt < 8; nt++) {
                const int c0 = colBase + nW + nt * 8 + 2 * cc;
                *(float2*)(out + (size_t)r * D_DIM + c0) =
                    make_float2(acc[mt][nt][hf * 2] * sc, acc[mt][nt][hf * 2 + 1] * sc);
            }
        }
}

// ===== kv TT fp16 GEMM: BK=64 rows per stage, 3 stages, 32 iterations =====
#define LKV 136
#define KV_STG_H (64 * LKV)
#define KV_STG_B (KV_STG_H * 2)        // 17408 B
#define KV_SMEM (3 * 2 * KV_STG_B)     // 104448 B

__global__ void __launch_bounds__(256, 2) k_gemm_kv() {
    extern __shared__ __align__(16) char smraw[];
    __half* Asm = (__half*)smraw;
    __half* Bsm = (__half*)(smraw + 3 * KV_STG_B);

    const int tid = threadIdx.x;
    const int wid = tid >> 5, lane = tid & 31;
    const int wr = wid & 3, wc = wid >> 2;
    const int mW = wr * 32, nW = wc * 64;
    const int rowBase = blockIdx.y * 128;   // d
    const int colBase = blockIdx.x * 128;   // m
    const int kBeg = blockIdx.z * (N_PTS / KV_SPLIT);
    float* C = g_kvpart + (size_t)blockIdx.z * D_DIM * M_FEAT;

    const uint32_t aB = smem_u32(Asm), bB = smem_u32(Bsm);

    auto stage = [&](uint32_t so, int kb) {
#pragma unroll
        for (int i = 0; i < 4; i++) {           // 64 n-rows x 128 halves per operand
            const int c = tid + i * 256;
            const int row = c >> 4;
            const int ch = (c & 15) * 8;
            cp_async16(aB + so + (row * LKV + ch) * 2,
                       g_chih + (size_t)(kb + row) * D_DIM + rowBase + ch);
            cp_async16(bB + so + (row * LKV + ch) * 2,
                       g_kph + (size_t)(kb + row) * M_FEAT + colBase + ch);
        }
        cp_commit();
    };

    float acc[2][8][4];
#pragma unroll
    for (int mt = 0; mt < 2; mt++)
#pragma unroll
        for (int nt = 0; nt < 8; nt++)
#pragma unroll
            for (int j = 0; j < 4; j++) acc[mt][nt][j] = 0.f;

    const int nk = (N_PTS / KV_SPLIT) / 64;      // 32
    stage(0, kBeg);
    stage(KV_STG_B, kBeg + 64);
    const int rr = lane >> 2, cc = lane & 3;
    const int lrow = lane & 15, lsel = (lane >> 4) << 3;

    const uint32_t aBase = aB + (lrow * LKV + mW + lsel) * 2;
    const uint32_t bBase = bB + (lrow * LKV + nW + lsel) * 2;

    uint32_t cso = 0, sso = 2 * KV_STG_B;
    for (int kt = 0; kt < nk; kt++) {
        cp_wait<1>();
        __syncthreads();
        if (kt + 2 < nk) {
            stage(sso, kBeg + (kt + 2) * 64);
            sso += KV_STG_B; if (sso == 3 * KV_STG_B) sso = 0;
        }
#pragma unroll
        for (int ks = 0; ks < 4; ks++) {
            const uint32_t ko = cso + ks * (16 * LKV * 2);
            uint32_t a[2][4], b[8][2];
#pragma unroll
            for (int mt = 0; mt < 2; mt++) {
                uint32_t r0, r1, r2, r3;
                ldsm_x4_t(r0, r1, r2, r3, aBase + ko + mt * 32);
                a[mt][0] = r0; a[mt][1] = r2; a[mt][2] = r1; a[mt][3] = r3;
            }
#pragma unroll
            for (int p = 0; p < 4; p++) {
                uint32_t r0, r1, r2, r3;
                ldsm_x4_t(r0, r1, r2, r3, bBase + ko + p * 32);
                b[2 * p][0] = r0; b[2 * p][1] = r1;
                b[2 * p + 1][0] = r2; b[2 * p + 1][1] = r3;
            }
#pragma unroll
            for (int mt = 0; mt < 2; mt++)
#pragma unroll
                for (int nt = 0; nt < 8; nt++)
                    mma_f16(acc[mt][nt], a[mt], b[nt]);
        }
        cso += KV_STG_B; if (cso == 3 * KV_STG_B) cso = 0;
    }

#pragma unroll
    for (int mt = 0; mt < 2; mt++)
#pragma unroll
        for (int hf = 0; hf < 2; hf++) {
            const int r = rowBase + mW + mt * 16 + rr + hf * 8;
#pragma unroll
            for (int nt = 0; nt < 8; nt++) {
                const int c0 = colBase + nW + nt * 8 + 2 * cc;
                *(float2*)(C + (size_t)r * M_FEAT + c0) =
                    make_float2(acc[mt][nt][hf * 2], acc[mt][nt][hf * 2 + 1]);
            }
        }
}

// ---------------- prep GEMM: Bq/Bk = proj @ W^T -> fp16 ----------------
#define BM 128
#define BN 128
#define BK 8
__global__ void __launch_bounds__(256) k_prep(const float* __restrict__ proj,
                                              const float* __restrict__ Wq,
                                              const float* __restrict__ Wk) {
    const float* B = blockIdx.z ? Wk : Wq;
    __half* C = blockIdx.z ? g_Bkh : g_Bqh;
    __shared__ float As[BK][BM];
    __shared__ float Bs[BK][BN];
    const int tid = threadIdx.x;
    const int tx = tid & 15, ty = tid >> 4;
    const int rowBase = blockIdx.y * BM, colBase = blockIdx.x * BN;
    const int rA = tid >> 1, cA = (tid & 1) * 4;

    float acc[8][8];
#pragma unroll
    for (int i = 0; i < 8; i++)
#pragma unroll
        for (int j = 0; j < 8; j++) acc[i][j] = 0.f;

    for (int kb = 0; kb < D_DIM; kb += BK) {
        float4 av = *(const float4*)(proj + (rowBase + rA) * D_DIM + kb + cA);
        float4 bv = *(const float4*)(B + (colBase + rA) * D_DIM + kb + cA);
        __syncthreads();
        As[cA + 0][rA] = av.x; As[cA + 1][rA] = av.y; As[cA + 2][rA] = av.z; As[cA + 3][rA] = av.w;
        Bs[cA + 0][rA] = bv.x; Bs[cA + 1][rA] = bv.y; Bs[cA + 2][rA] = bv.z; Bs[cA + 3][rA] = bv.w;
        __syncthreads();
#pragma unroll
        for (int k = 0; k < BK; k++) {
            float a[8], b[8];
#pragma unroll
            for (int i = 0; i < 8; i++) a[i] = As[k][ty * 8 + i];
#pragma unroll
            for (int j = 0; j < 8; j++) b[j] = Bs[k][tx * 8 + j];
#pragma unroll
            for (int i = 0; i < 8; i++)
#pragma unroll
                for (int j = 0; j < 8; j++) acc[i][j] = fmaf(a[i], b[j], acc[i][j]);
        }
    }
#pragma unroll
    for (int i = 0; i < 8; i++) {
        __half* cp = C + (rowBase + ty * 8 + i) * D_DIM + colBase + tx * 8;
#pragma unroll
        for (int j = 0; j < 8; j++) cp[j] = __float2half_rn(acc[i][j]);
    }
}

__global__ void k_bias(const float* __restrict__ bq, const float* __restrict__ bk,
                       const float* __restrict__ proj) {
    int m = blockIdx.x * blockDim.x + threadIdx.x;
    const float* b = blockIdx.y ? bk : bq;
    float* c = blockIdx.y ? g_ck : g_cq;
    float s = 0.f;
    for (int j = 0; j < D_DIM; j++) s += b[j] * proj[m * D_DIM + j];
    c[m] = s;
}

// x -> g_xh (z=0), chi -> g_chih (z=1)
__global__ void k_cvt(const float* __restrict__ x, const float* __restrict__ chi) {
    const float* src = blockIdx.z ? chi : x;
    __half* dst = blockIdx.z ? g_chih : g_xh;
    size_t i = ((size_t)blockIdx.x * 256 + threadIdx.x) * 8;
    float4 v0 = *(const float4*)(src + i);
    float4 v1 = *(const float4*)(src + i + 4);
    half2 h0 = __floats2half2_rn(v0.x, v0.y);
    half2 h1 = __floats2half2_rn(v0.z, v0.w);
    half2 h2 = __floats2half2_rn(v1.x, v1.y);
    half2 h3 = __floats2half2_rn(v1.z, v1.w);
    uint4 o = make_uint4(*(uint32_t*)&h0, *(uint32_t*)&h1, *(uint32_t*)&h2, *(uint32_t*)&h3);
    *(uint4*)(dst + i) = o;
}

__global__ void k_colsum2() {
    int m = blockIdx.x * 32 + threadIdx.x;
    float s = 0.f;
    for (int y = 0; y < QK_YB; y++) s += g_ks_part[y * M_FEAT + m];
    g_ks[m] = s;
}

__global__ void k_kvred() {
    int i = blockIdx.x * blockDim.x + threadIdx.x;
    float s = 0.f;
#pragma unroll
    for (int z = 0; z < KV_SPLIT; z++) s += g_kvpart[(size_t)z * D_DIM * M_FEAT + i];
    g_kvh[i] = __float2half_rn(s);
}

// ---------------- launch ----------------
extern "C" void kernel_launch(void* const* d_in, const int* in_sizes, int n_in,
                              void* d_out, int out_size) {
    const float* chi  = (const float*)d_in[0];
    const float* x    = (const float*)d_in[1];
    const float* Wq   = (const float*)d_in[2];
    const float* bq   = (const float*)d_in[3];
    const float* Wk   = (const float*)d_in[4];
    const float* bk   = (const float*)d_in[5];
    const float* proj = (const float*)d_in[6];
    float* out = (float*)d_out;

    cudaFuncSetAttribute(k_gemm_qk,  cudaFuncAttributeMaxDynamicSharedMemorySize, NT_SMEM);
    cudaFuncSetAttribute(k_gemm_num, cudaFuncAttributeMaxDynamicSharedMemorySize, NT_SMEM);
    cudaFuncSetAttribute(k_gemm_kv,  cudaFuncAttributeMaxDynamicSharedMemorySize, KV_SMEM);

    k_prep<<<dim3(D_DIM / BN, M_FEAT / BM, 2), 256>>>(proj, Wq, Wk);
    k_bias<<<dim3(2, 2), 256>>>(bq, bk, proj);
    k_cvt<<<dim3((N_PTS * D_DIM) / (256 * 8), 1, 2), 256>>>(x, chi);
    k_gemm_qk<<<dim3(M_FEAT / 128, N_PTS / 128, 2), 256, NT_SMEM>>>();
    k_colsum2<<<16, 32>>>();
    k_gemm_kv<<<dim3(M_FEAT / 128, D_DIM / 128, KV_SPLIT), 256, KV_SMEM>>>();
    k_kvred<<<(D_DIM * M_FEAT) / 256, 256>>>();
    k_gemm_num<<<dim3(D_DIM / 128, N_PTS / 128), 256, NT_SMEM>>>(out);
}

// round 16
// speedup vs baseline: 1.1181x; 1.0129x over previous
#include <cuda_runtime.h>
#include <cuda_fp16.h>
#include <cstdint>
#include <math.h>

// ---------------- problem constants ----------------
#define N_PTS 32768
#define D_DIM 512
#define M_FEAT 512
#define KEPS 0.001f
#define NSTAB 1e-6f
#define KV_SPLIT 16
#define QK_YB (N_PTS / 128)     // 256

// ---------------- scratch ----------------
__device__ __half g_xh[(size_t)N_PTS * D_DIM];
__device__ __half g_chih[(size_t)N_PTS * D_DIM];
__device__ __half g_Bqh[M_FEAT * D_DIM];
__device__ __half g_Bkh[M_FEAT * D_DIM];
__device__ float g_cq[M_FEAT];
__device__ float g_ck[M_FEAT];
__device__ __half g_qph[(size_t)N_PTS * M_FEAT];
__device__ __half g_kph[(size_t)N_PTS * M_FEAT];
__device__ float g_ks_part[QK_YB * M_FEAT];
__device__ float g_ks[M_FEAT];
__device__ float g_kvpart[(size_t)KV_SPLIT * D_DIM * M_FEAT];
__device__ __half g_kvh[D_DIM * M_FEAT];

// ---------------- helpers ----------------
__device__ __forceinline__ uint32_t smem_u32(const void* p) {
    uint32_t a;
    asm("{ .reg .u64 t; cvta.to.shared.u64 t, %1; cvt.u32.u64 %0, t; }" : "=r"(a) : "l"(p));
    return a;
}
__device__ __forceinline__ void cp_async16(uint32_t saddr, const void* gptr) {
    asm volatile("cp.async.cg.shared.global [%0], [%1], 16;" :: "r"(saddr), "l"(gptr) : "memory");
}
__device__ __forceinline__ void cp_commit() { asm volatile("cp.async.commit_group;" ::: "memory"); }
template<int N>
__device__ __forceinline__ void cp_wait() { asm volatile("cp.async.wait_group %0;" :: "n"(N) : "memory"); }

__device__ __forceinline__ void mma_f16(float* c, const uint32_t* a, const uint32_t* b) {
    asm volatile(
        "mma.sync.aligned.m16n8k16.row.col.f32.f16.f16.f32 "
        "{%0,%1,%2,%3}, {%4,%5,%6,%7}, {%8,%9}, {%0,%1,%2,%3};"
        : "+f"(c[0]), "+f"(c[1]), "+f"(c[2]), "+f"(c[3])
        : "r"(a[0]), "r"(a[1]), "r"(a[2]), "r"(a[3]), "r"(b[0]), "r"(b[1]));
}
__device__ __forceinline__ void ldsm_x4(uint32_t& r0, uint32_t& r1, uint32_t& r2, uint32_t& r3,
                                        uint32_t addr) {
    asm volatile("ldmatrix.sync.aligned.m8n8.x4.shared.b16 {%0,%1,%2,%3}, [%4];"
                 : "=r"(r0), "=r"(r1), "=r"(r2), "=r"(r3) : "r"(addr));
}
__device__ __forceinline__ void ldsm_x4_t(uint32_t& r0, uint32_t& r1, uint32_t& r2, uint32_t& r3,
                                          uint32_t addr) {
    asm volatile("ldmatrix.sync.aligned.m8n8.x4.trans.shared.b16 {%0,%1,%2,%3}, [%4];"
                 : "=r"(r0), "=r"(r1), "=r"(r2), "=r"(r3) : "r"(addr));
}

// ======= NT fp16 GEMM: 128x128 tile, 8 warps (4m x 2n), BK=64, 3 stages =======
#define LQH 72
#define NT_STG_H (128 * LQH)
#define NT_STG_B (NT_STG_H * 2)       // 18432 B
#define NT_SMEM (3 * 2 * NT_STG_B)    // 110592 B

// qk body: q'/k' = relu(x @ B^T + c) + eps. isK selects weights/output + colsum path.
__device__ __forceinline__ void qk_body(char* smraw, bool isK, int colBlock, int rowBlock) {
    __half* Asm = (__half*)smraw;
    __half* Bsm = (__half*)(smraw + 3 * NT_STG_B);
    __shared__ float scol[4][128];

    const int tid = threadIdx.x;
    const int wid = tid >> 5, lane = tid & 31;
    const int wr = wid & 3, wc = wid >> 2;
    const int mW = wr * 32, nW = wc * 64;
    const int rowBase = rowBlock * 128;
    const int colBase = colBlock * 128;
    const __half* Bg = isK ? g_Bkh : g_Bqh;
    const float* ev = isK ? g_ck : g_cq;

    const uint32_t aB = smem_u32(Asm), bB = smem_u32(Bsm);

    auto stage = [&](uint32_t so, int kb) {
#pragma unroll
        for (int i = 0; i < 4; i++) {
            const int c = tid + i * 256;
            const int row = c >> 3;
            const int ch = (c & 7) * 8;
            cp_async16(aB + so + (row * LQH + ch) * 2,
                       g_xh + (size_t)(rowBase + row) * D_DIM + kb + ch);
            cp_async16(bB + so + (row * LQH + ch) * 2,
                       Bg + (size_t)(colBase + row) * D_DIM + kb + ch);
        }
        cp_commit();
    };

    float acc[2][8][4];
#pragma unroll
    for (int mt = 0; mt < 2; mt++)
#pragma unroll
        for (int nt = 0; nt < 8; nt++)
#pragma unroll
            for (int j = 0; j < 4; j++) acc[mt][nt][j] = 0.f;

    const int nk = D_DIM / 64;   // 8
    stage(0, 0); stage(NT_STG_B, 64);
    const int rr = lane >> 2, cc = lane & 3;
    const int lrow = lane & 15, lsel = (lane >> 4) << 3;

    const uint32_t aBase = aB + ((mW + lrow) * LQH + lsel) * 2;
    const uint32_t bBase = bB + ((nW + lrow) * LQH + lsel) * 2;

    uint32_t cso = 0, sso = 2 * NT_STG_B;
    for (int kt = 0; kt < nk; kt++) {
        cp_wait<1>();
        __syncthreads();
        if (kt + 2 < nk) {
            stage(sso, (kt + 2) * 64);
            sso += NT_STG_B; if (sso == 3 * NT_STG_B) sso = 0;
        }
#pragma unroll
        for (int ks = 0; ks < 4; ks++) {
            const uint32_t ko = cso + ks * 32;
            uint32_t a[2][4], b[8][2];
#pragma unroll
            for (int mt = 0; mt < 2; mt++)
                ldsm_x4(a[mt][0], a[mt][1], a[mt][2], a[mt][3],
                        aBase + ko + mt * (16 * LQH * 2));
#pragma unroll
            for (int p = 0; p < 4; p++) {
                uint32_t r0, r1, r2, r3;
                ldsm_x4(r0, r1, r2, r3, bBase + ko + p * (16 * LQH * 2));
                b[2 * p][0] = r0; b[2 * p][1] = r2;
                b[2 * p + 1][0] = r1; b[2 * p + 1][1] = r3;
            }
#pragma unroll
            for (int mt = 0; mt < 2; mt++)
#pragma unroll
                for (int nt = 0; nt < 8; nt++)
                    mma_f16(acc[mt][nt], a[mt], b[nt]);
        }
        cso += NT_STG_B; if (cso == 3 * NT_STG_B) cso = 0;
    }

    if (!isK) {
#pragma unroll
        for (int mt = 0; mt < 2; mt++)
#pragma unroll
            for (int hf = 0; hf < 2; hf++) {
                const int r = rowBase + mW + mt * 16 + rr + hf * 8;
#pragma unroll
                for (int nt = 0; nt < 8; nt++) {
                    const int c0 = colBase + nW + nt * 8 + 2 * cc;
                    float v0 = fmaxf(acc[mt][nt][hf * 2] + ev[c0], 0.f) + KEPS;
                    float v1 = fmaxf(acc[mt][nt][hf * 2 + 1] + ev[c0 + 1], 0.f) + KEPS;
                    *(half2*)(g_qph + (size_t)r * M_FEAT + c0) = __floats2half2_rn(v0, v1);
                }
            }
    } else {
        float cs[8][2];
#pragma unroll
        for (int nt = 0; nt < 8; nt++) { cs[nt][0] = 0.f; cs[nt][1] = 0.f; }
#pragma unroll
        for (int mt = 0; mt < 2; mt++)
#pragma unroll
            for (int hf = 0; hf < 2; hf++) {
                const int r = rowBase + mW + mt * 16 + rr + hf * 8;
#pragma unroll
                for (int nt = 0; nt < 8; nt++) {
                    const int c0 = colBase + nW + nt * 8 + 2 * cc;
                    float v0 = fmaxf(acc[mt][nt][hf * 2] + ev[c0], 0.f) + KEPS;
                    float v1 = fmaxf(acc[mt][nt][hf * 2 + 1] + ev[c0 + 1], 0.f) + KEPS;
                    *(half2*)(g_kph + (size_t)r * M_FEAT + c0) = __floats2half2_rn(v0, v1);
                    cs[nt][0] += v0; cs[nt][1] += v1;
                }
            }
#pragma unroll
        for (int nt = 0; nt < 8; nt++)
#pragma unroll
            for (int j = 0; j < 2; j++) {
                float s = cs[nt][j];
                s += __shfl_xor_sync(0xffffffffu, s, 4);
                s += __shfl_xor_sync(0xffffffffu, s, 8);
                s += __shfl_xor_sync(0xffffffffu, s, 16);
                cs[nt][j] = s;
            }
        if (rr == 0) {
#pragma unroll
            for (int nt = 0; nt < 8; nt++) {
                scol[wr][nW + nt * 8 + 2 * cc] = cs[nt][0];
                scol[wr][nW + nt * 8 + 2 * cc + 1] = cs[nt][1];
            }
        }
        __syncthreads();
        if (tid < 128)
            g_ks_part[rowBlock * M_FEAT + colBase + tid] =
                scol[0][tid] + scol[1][tid] + scol[2][tid] + scol[3][tid];
    }
}

// ===== kv TT fp16 body: kvT[d,m] = sum_n chih[n,d]*kph[n,m], BK=64, 3 stages =====
#define LKV 136
#define KV_STG_H (64 * LKV)
#define KV_STG_B (KV_STG_H * 2)        // 17408 B
#define KV_SMEM (3 * 2 * KV_STG_B)     // 104448 B

__device__ __forceinline__ void kv_body(char* smraw, int mBlock, int dBlock, int split) {
    __half* Asm = (__half*)smraw;
    __half* Bsm = (__half*)(smraw + 3 * KV_STG_B);

    const int tid = threadIdx.x;
    const int wid = tid >> 5, lane = tid & 31;
    const int wr = wid & 3, wc = wid >> 2;
    const int mW = wr * 32, nW = wc * 64;
    const int rowBase = dBlock * 128;
    const int colBase = mBlock * 128;
    const int kBeg = split * (N_PTS / KV_SPLIT);
    float* C = g_kvpart + (size_t)split * D_DIM * M_FEAT;

    const uint32_t aB = smem_u32(Asm), bB = smem_u32(Bsm);

    auto stage = [&](uint32_t so, int kb) {
#pragma unroll
        for (int i = 0; i < 4; i++) {
            const int c = tid + i * 256;
            const int row = c >> 4;
            const int ch = (c & 15) * 8;
            cp_async16(aB + so + (row * LKV + ch) * 2,
                       g_chih + (size_t)(kb + row) * D_DIM + rowBase + ch);
            cp_async16(bB + so + (row * LKV + ch) * 2,
                       g_kph + (size_t)(kb + row) * M_FEAT + colBase + ch);
        }
        cp_commit();
    };

    float acc[2][8][4];
#pragma unroll
    for (int mt = 0; mt < 2; mt++)
#pragma unroll
        for (int nt = 0; nt < 8; nt++)
#pragma unroll
            for (int j = 0; j < 4; j++) acc[mt][nt][j] = 0.f;

    const int nk = (N_PTS / KV_SPLIT) / 64;      // 32
    stage(0, kBeg);
    stage(KV_STG_B, kBeg + 64);
    const int rr = lane >> 2, cc = lane & 3;
    const int lrow = lane & 15, lsel = (lane >> 4) << 3;

    const uint32_t aBase = aB + (lrow * LKV + mW + lsel) * 2;
    const uint32_t bBase = bB + (lrow * LKV + nW + lsel) * 2;

    uint32_t cso = 0, sso = 2 * KV_STG_B;
    for (int kt = 0; kt < nk; kt++) {
        cp_wait<1>();
        __syncthreads();
        if (kt + 2 < nk) {
            stage(sso, kBeg + (kt + 2) * 64);
            sso += KV_STG_B; if (sso == 3 * KV_STG_B) sso = 0;
        }
#pragma unroll
        for (int ks = 0; ks < 4; ks++) {
            const uint32_t ko = cso + ks * (16 * LKV * 2);
            uint32_t a[2][4], b[8][2];
#pragma unroll
            for (int mt = 0; mt < 2; mt++) {
                uint32_t r0, r1, r2, r3;
                ldsm_x4_t(r0, r1, r2, r3, aBase + ko + mt * 32);
                a[mt][0] = r0; a[mt][1] = r2; a[mt][2] = r1; a[mt][3] = r3;
            }
#pragma unroll
            for (int p = 0; p < 4; p++) {
                uint32_t r0, r1, r2, r3;
                ldsm_x4_t(r0, r1, r2, r3, bBase + ko + p * 32);
                b[2 * p][0] = r0; b[2 * p][1] = r1;
                b[2 * p + 1][0] = r2; b[2 * p + 1][1] = r3;
            }
#pragma unroll
            for (int mt = 0; mt < 2; mt++)
#pragma unroll
                for (int nt = 0; nt < 8; nt++)
                    mma_f16(acc[mt][nt], a[mt], b[nt]);
        }
        cso += KV_STG_B; if (cso == 3 * KV_STG_B) cso = 0;
    }

#pragma unroll
    for (int mt = 0; mt < 2; mt++)
#pragma unroll
        for (int hf = 0; hf < 2; hf++) {
            const int r = rowBase + mW + mt * 16 + rr + hf * 8;
#pragma unroll
            for (int nt = 0; nt < 8; nt++) {
                const int c0 = colBase + nW + nt * 8 + 2 * cc;
                *(float2*)(C + (size_t)r * M_FEAT + c0) =
                    make_float2(acc[mt][nt][hf * 2], acc[mt][nt][hf * 2 + 1]);
            }
        }
}

// ---------------- launched kernels ----------------

// qk k-side only (feeds kv)
__global__ void __launch_bounds__(256, 2) k_gemm_qk_k() {
    extern __shared__ __align__(16) char smraw[];
    qk_body(smraw, true, blockIdx.x, blockIdx.y);
}

// fused: kv blocks (y<64) + qk q-side blocks (64<=y<320) + colsum blocks (y==320)
__global__ void __launch_bounds__(256, 2) k_fused() {
    extern __shared__ __align__(16) char smraw[];
    const int y = blockIdx.y;
    if (y < 64) {
        kv_body(smraw, blockIdx.x, y >> 4, y & 15);
    } else if (y < 320) {
        qk_body(smraw, false, blockIdx.x, y - 64);
    } else {
        // colsum: block x handles m range [x*128, x*128+128)
        const int m = blockIdx.x * 128 + (threadIdx.x & 127);
        if (threadIdx.x < 128) {
            float s = 0.f;
            for (int yb = 0; yb < QK_YB; yb++) s += g_ks_part[yb * M_FEAT + m];
            g_ks[m] = s;
        }
    }
}

// num: out = (qph @ kvh^T) * 1/den, den fused
__global__ void __launch_bounds__(256, 2) k_gemm_num(float* __restrict__ out) {
    extern __shared__ __align__(16) char smraw[];
    __half* Asm = (__half*)smraw;
    __half* Bsm = (__half*)(smraw + 3 * NT_STG_B);
    __shared__ float kss[512];

    const int tid = threadIdx.x;
    const int wid = tid >> 5, lane = tid & 31;
    const int wr = wid & 3, wc = wid >> 2;
    const int mW = wr * 32, nW = wc * 64;
    const int rowBase = blockIdx.y * 128;
    const int colBase = blockIdx.x * 128;

    kss[tid] = g_ks[tid];
    kss[tid + 256] = g_ks[tid + 256];

    const uint32_t aB = smem_u32(Asm), bB = smem_u32(Bsm);

    auto stage = [&](uint32_t so, int kb) {
#pragma unroll
        for (int i = 0; i < 4; i++) {
            const int c = tid + i * 256;
            const int row = c >> 3;
            const int ch = (c & 7) * 8;
            cp_async16(aB + so + (row * LQH + ch) * 2,
                       g_qph + (size_t)(rowBase + row) * M_FEAT + kb + ch);
            cp_async16(bB + so + (row * LQH + ch) * 2,
                       g_kvh + (size_t)(colBase + row) * M_FEAT + kb + ch);
        }
        cp_commit();
    };

    float acc[2][8][4];
#pragma unroll
    for (int mt = 0; mt < 2; mt++)
#pragma unroll
        for (int nt = 0; nt < 8; nt++)
#pragma unroll
            for (int j = 0; j < 4; j++) acc[mt][nt][j] = 0.f;
    float den[2][2] = {{0.f, 0.f}, {0.f, 0.f}};

    const int nk = M_FEAT / 64;  // 8
    stage(0, 0); stage(NT_STG_B, 64);
    const int rr = lane >> 2, cc = lane & 3;
    const int lrow = lane & 15, lsel = (lane >> 4) << 3;

    const uint32_t aBase = aB + ((mW + lrow) * LQH + lsel) * 2;
    const uint32_t bBase = bB + ((nW + lrow) * LQH + lsel) * 2;

    uint32_t cso = 0, sso = 2 * NT_STG_B;
    for (int kt = 0; kt < nk; kt++) {
        cp_wait<1>();
        __syncthreads();
        if (kt + 2 < nk) {
            stage(sso, (kt + 2) * 64);
            sso += NT_STG_B; if (sso == 3 * NT_STG_B) sso = 0;
        }
#pragma unroll
        for (int ks = 0; ks < 4; ks++) {
            const uint32_t ko = cso + ks * 32;
            uint32_t a[2][4], b[8][2];
#pragma unroll
            for (int mt = 0; mt < 2; mt++)
                ldsm_x4(a[mt][0], a[mt][1], a[mt][2], a[mt][3],
                        aBase + ko + mt * (16 * LQH * 2));
#pragma unroll
            for (int p = 0; p < 4; p++) {
                uint32_t r0, r1, r2, r3;
                ldsm_x4(r0, r1, r2, r3, bBase + ko + p * (16 * LQH * 2));
                b[2 * p][0] = r0; b[2 * p][1] = r2;
                b[2 * p + 1][0] = r1; b[2 * p + 1][1] = r3;
            }
            const int kbase = kt * 64 + ks * 16;
            const float2 kA = *(const float2*)&kss[kbase + 2 * cc];
            const float2 kB = *(const float2*)&kss[kbase + 8 + 2 * cc];
#pragma unroll
            for (int mt = 0; mt < 2; mt++) {
                float2 a0 = __half22float2(*(const half2*)&a[mt][0]);
                float2 a1 = __half22float2(*(const half2*)&a[mt][1]);
                float2 a2 = __half22float2(*(const half2*)&a[mt][2]);
                float2 a3 = __half22float2(*(const half2*)&a[mt][3]);
                den[mt][0] += a0.x * kA.x + a0.y * kA.y + a2.x * kB.x + a2.y * kB.y;
                den[mt][1] += a1.x * kA.x + a1.y * kA.y + a3.x * kB.x + a3.y * kB.y;
            }
#pragma unroll
            for (int mt = 0; mt < 2; mt++)
#pragma unroll
                for (int nt = 0; nt < 8; nt++)
                    mma_f16(acc[mt][nt], a[mt], b[nt]);
        }
        cso += NT_STG_B; if (cso == 3 * NT_STG_B) cso = 0;
    }

    float inv[2][2];
#pragma unroll
    for (int mt = 0; mt < 2; mt++)
#pragma unroll
        for (int h = 0; h < 2; h++) {
            float d = den[mt][h];
            d += __shfl_xor_sync(0xffffffffu, d, 1);
            d += __shfl_xor_sync(0xffffffffu, d, 2);
            if (fabsf(d) <= NSTAB) d += 2.f * NSTAB;
            inv[mt][h] = 1.f / d;
        }

#pragma unroll
    for (int mt = 0; mt < 2; mt++)
#pragma unroll
        for (int hf = 0; hf < 2; hf++) {
            const int r = rowBase + mW + mt * 16 + rr + hf * 8;
            const float sc = inv[mt][hf];
#pragma unroll
            for (int nt = 0; nt < 8; nt++) {
                const int c0 = colBase + nW + nt * 8 + 2 * cc;
                *(float2*)(out + (size_t)r * D_DIM + c0) =
                    make_float2(acc[mt][nt][hf * 2] * sc, acc[mt][nt][hf * 2 + 1] * sc);
            }
        }
}

// ---------------- fused front kernel: cvt(x,chi) + prep(Bq/Bk) + bias ----------------
// flat grid: [0,8192) cvt x ; [8192,16384) cvt chi ; [16384,16416) prep ; [16416,16420) bias
__global__ void __launch_bounds__(256) k_pre(const float* __restrict__ x,
                                             const float* __restrict__ chi,
                                             const float* __restrict__ Wq,
                                             const float* __restrict__ Wk,
                                             const float* __restrict__ bq,
                                             const float* __restrict__ bk,
                                             const float* __restrict__ proj) {
    const int bid = blockIdx.x;
    const int tid = threadIdx.x;

    if (bid < 16384) {                        // cvt
        const bool isChi = (bid >= 8192);
        const float* src = isChi ? chi : x;
        __half* dst = isChi ? g_chih : g_xh;
        size_t i = ((size_t)(bid & 8191) * 256 + tid) * 8;
        float4 v0 = *(const float4*)(src + i);
        float4 v1 = *(const float4*)(src + i + 4);
        half2 h0 = __floats2half2_rn(v0.x, v0.y);
        half2 h1 = __floats2half2_rn(v0.z, v0.w);
        half2 h2 = __floats2half2_rn(v1.x, v1.y);
        half2 h3 = __floats2half2_rn(v1.z, v1.w);
        uint4 o = make_uint4(*(uint32_t*)&h0, *(uint32_t*)&h1, *(uint32_t*)&h2, *(uint32_t*)&h3);
        *(uint4*)(dst + i) = o;
    } else if (bid < 16416) {                 // prep: Bq/Bk = proj @ W^T -> fp16
        const int pb = bid - 16384;
        const int zb = pb >> 4;               // 0=q, 1=k
        const int xb = pb & 3, yb = (pb >> 2) & 3;
        const float* B = zb ? Wk : Wq;
        __half* C = zb ? g_Bkh : g_Bqh;
        __shared__ float As[8][128];
        __shared__ float Bs[8][128];
        const int tx = tid & 15, ty = tid >> 4;
        const int rowBase = yb * 128, colBase = xb * 128;
        const int rA = tid >> 1, cA = (tid & 1) * 4;

        float acc[8][8];
#pragma unroll
        for (int i = 0; i < 8; i++)
#pragma unroll
            for (int j = 0; j < 8; j++) acc[i][j] = 0.f;

        for (int kb = 0; kb < D_DIM; kb += 8) {
            float4 av = *(const float4*)(proj + (rowBase + rA) * D_DIM + kb + cA);
            float4 bv = *(const float4*)(B + (colBase + rA) * D_DIM + kb + cA);
            __syncthreads();
            As[cA + 0][rA] = av.x; As[cA + 1][rA] = av.y; As[cA + 2][rA] = av.z; As[cA + 3][rA] = av.w;
            Bs[cA + 0][rA] = bv.x; Bs[cA + 1][rA] = bv.y; Bs[cA + 2][rA] = bv.z; Bs[cA + 3][rA] = bv.w;
            __syncthreads();
#pragma unroll
            for (int k = 0; k < 8; k++) {
                float a[8], b[8];
#pragma unroll
                for (int i = 0; i < 8; i++) a[i] = As[k][ty * 8 + i];
#pragma unroll
                for (int j = 0; j < 8; j++) b[j] = Bs[k][tx * 8 + j];
#pragma unroll
                for (int i = 0; i < 8; i++)
#pragma unroll
                    for (int j = 0; j < 8; j++) acc[i][j] = fmaf(a[i], b[j], acc[i][j]);
            }
        }
#pragma unroll
        for (int i = 0; i < 8; i++) {
            __half* cp = C + (rowBase + ty * 8 + i) * D_DIM + colBase + tx * 8;
#pragma unroll
            for (int j = 0; j < 8; j++) cp[j] = __float2half_rn(acc[i][j]);
        }
    } else {                                  // bias: cq/ck = b @ proj^T
        const int b2 = bid - 16416;
        const int xb = b2 & 1, yb = b2 >> 1;
        const int m = xb * 256 + tid;
        const float* b = yb ? bk : bq;
        float* c = yb ? g_ck : g_cq;
        float s = 0.f;
        for (int j = 0; j < D_DIM; j++) s += b[j] * proj[m * D_DIM + j];
        c[m] = s;
    }
}

__global__ void k_kvred() {
    int i = blockIdx.x * blockDim.x + threadIdx.x;
    float s = 0.f;
#pragma unroll
    for (int z = 0; z < KV_SPLIT; z++) s += g_kvpart[(size_t)z * D_DIM * M_FEAT + i];
    g_kvh[i] = __float2half_rn(s);
}

// ---------------- launch ----------------
extern "C" void kernel_launch(void* const* d_in, const int* in_sizes, int n_in,
                              void* d_out, int out_size) {
    const float* chi  = (const float*)d_in[0];
    const float* x    = (const float*)d_in[1];
    const float* Wq   = (const float*)d_in[2];
    const float* bq   = (const float*)d_in[3];
    const float* Wk   = (const float*)d_in[4];
    const float* bk   = (const float*)d_in[5];
    const float* proj = (const float*)d_in[6];
    float* out = (float*)d_out;

    cudaFuncSetAttribute(k_gemm_qk_k, cudaFuncAttributeMaxDynamicSharedMemorySize, NT_SMEM);
    cudaFuncSetAttribute(k_fused,     cudaFuncAttributeMaxDynamicSharedMemorySize, NT_SMEM);
    cudaFuncSetAttribute(k_gemm_num,  cudaFuncAttributeMaxDynamicSharedMemorySize, NT_SMEM);

    // 1) fused front: cvt x/chi + prep Bq/Bk + bias
    k_pre<<<16420, 256>>>(x, chi, Wq, Wk, bq, bk, proj);
    // 2) k' (+ colsum partials)
    k_gemm_qk_k<<<dim3(M_FEAT / 128, N_PTS / 128), 256, NT_SMEM>>>();
    // 3) fused: kv GEMM (y<64) + q' GEMM (64<=y<320) + colsum finalize (y==320)
    k_fused<<<dim3(4, 321), 256, NT_SMEM>>>();
    // 4) kv partial reduce -> fp16
    k_kvred<<<(D_DIM * M_FEAT) / 256, 256>>>();
    // 5) out = (q' @ kvT^T) * 1/den
    k_gemm_num<<<dim3(D_DIM / 128, N_PTS / 128), 256, NT_SMEM>>>(out);
}

// round 17
// speedup vs baseline: 1.1577x; 1.0354x over previous
#include <cuda_runtime.h>
#include <cuda_fp16.h>
#include <cstdint>
#include <math.h>

// ---------------- problem constants ----------------
#define N_PTS 32768
#define D_DIM 512
#define M_FEAT 512
#define KEPS 0.001f
#define NSTAB 1e-6f
#define KV_SPLIT 16
#define QK_YB (N_PTS / 128)     // 256

// ---------------- scratch ----------------
__device__ __half g_xh[(size_t)N_PTS * D_DIM];
__device__ __half g_chih[(size_t)N_PTS * D_DIM];
__device__ __half g_Bqh[M_FEAT * D_DIM];
__device__ __half g_Bkh[M_FEAT * D_DIM];
__device__ float g_cq[M_FEAT];
__device__ float g_ck[M_FEAT];
__device__ __half g_qph[(size_t)N_PTS * M_FEAT];
__device__ __half g_kph[(size_t)N_PTS * M_FEAT];
__device__ float g_ks_part[QK_YB * M_FEAT];
__device__ float g_ks[M_FEAT];
__device__ float g_kvpart[(size_t)KV_SPLIT * D_DIM * M_FEAT];
__device__ __half g_kvh[D_DIM * M_FEAT];

// ---------------- helpers ----------------
__device__ __forceinline__ uint32_t smem_u32(const void* p) {
    uint32_t a;
    asm("{ .reg .u64 t; cvta.to.shared.u64 t, %1; cvt.u32.u64 %0, t; }" : "=r"(a) : "l"(p));
    return a;
}
__device__ __forceinline__ void cp_async16(uint32_t saddr, const void* gptr) {
    asm volatile("cp.async.cg.shared.global [%0], [%1], 16;" :: "r"(saddr), "l"(gptr) : "memory");
}
__device__ __forceinline__ void cp_commit() { asm volatile("cp.async.commit_group;" ::: "memory"); }
template<int N>
__device__ __forceinline__ void cp_wait() { asm volatile("cp.async.wait_group %0;" :: "n"(N) : "memory"); }

__device__ __forceinline__ void mma_f16(float* c, const uint32_t* a, const uint32_t* b) {
    asm volatile(
        "mma.sync.aligned.m16n8k16.row.col.f32.f16.f16.f32 "
        "{%0,%1,%2,%3}, {%4,%5,%6,%7}, {%8,%9}, {%0,%1,%2,%3};"
        : "+f"(c[0]), "+f"(c[1]), "+f"(c[2]), "+f"(c[3])
        : "r"(a[0]), "r"(a[1]), "r"(a[2]), "r"(a[3]), "r"(b[0]), "r"(b[1]));
}
__device__ __forceinline__ void ldsm_x4(uint32_t& r0, uint32_t& r1, uint32_t& r2, uint32_t& r3,
                                        uint32_t addr) {
    asm volatile("ldmatrix.sync.aligned.m8n8.x4.shared.b16 {%0,%1,%2,%3}, [%4];"
                 : "=r"(r0), "=r"(r1), "=r"(r2), "=r"(r3) : "r"(addr));
}
__device__ __forceinline__ void ldsm_x4_t(uint32_t& r0, uint32_t& r1, uint32_t& r2, uint32_t& r3,
                                          uint32_t addr) {
    asm volatile("ldmatrix.sync.aligned.m8n8.x4.trans.shared.b16 {%0,%1,%2,%3}, [%4];"
                 : "=r"(r0), "=r"(r1), "=r"(r2), "=r"(r3) : "r"(addr));
}

// ======= NT fp16 GEMM: 128x128 tile, 8 warps (4m x 2n), BK=64, 3 stages =======
#define LQH 72
#define NT_STG_H (128 * LQH)
#define NT_STG_B (NT_STG_H * 2)       // 18432 B
#define NT_SMEM (3 * 2 * NT_STG_B)    // 110592 B

// qk body: q'/k' = relu(x @ B^T + c) + eps. isK selects weights/output + colsum path.
__device__ __forceinline__ void qk_body(char* smraw, bool isK, int colBlock, int rowBlock) {
    __half* Asm = (__half*)smraw;
    __half* Bsm = (__half*)(smraw + 3 * NT_STG_B);
    __shared__ float scol[4][128];

    const int tid = threadIdx.x;
    const int wid = tid >> 5, lane = tid & 31;
    const int wr = wid & 3, wc = wid >> 2;
    const int mW = wr * 32, nW = wc * 64;
    const int rowBase = rowBlock * 128;
    const int colBase = colBlock * 128;
    const __half* Bg = isK ? g_Bkh : g_Bqh;
    const float* ev = isK ? g_ck : g_cq;

    const uint32_t aB = smem_u32(Asm), bB = smem_u32(Bsm);

    auto stage = [&](uint32_t so, int kb) {
#pragma unroll
        for (int i = 0; i < 4; i++) {
            const int c = tid + i * 256;
            const int row = c >> 3;
            const int ch = (c & 7) * 8;
            cp_async16(aB + so + (row * LQH + ch) * 2,
                       g_xh + (size_t)(rowBase + row) * D_DIM + kb + ch);
            cp_async16(bB + so + (row * LQH + ch) * 2,
                       Bg + (size_t)(colBase + row) * D_DIM + kb + ch);
        }
        cp_commit();
    };

    float acc[2][8][4];
#pragma unroll
    for (int mt = 0; mt < 2; mt++)
#pragma unroll
        for (int nt = 0; nt < 8; nt++)
#pragma unroll
            for (int j = 0; j < 4; j++) acc[mt][nt][j] = 0.f;

    const int nk = D_DIM / 64;   // 8
    stage(0, 0); stage(NT_STG_B, 64);
    const int rr = lane >> 2, cc = lane & 3;
    const int lrow = lane & 15, lsel = (lane >> 4) << 3;

    const uint32_t aBase = aB + ((mW + lrow) * LQH + lsel) * 2;
    const uint32_t bBase = bB + ((nW + lrow) * LQH + lsel) * 2;

    uint32_t cso = 0, sso = 2 * NT_STG_B;
    for (int kt = 0; kt < nk; kt++) {
        cp_wait<1>();
        __syncthreads();
        if (kt + 2 < nk) {
            stage(sso, (kt + 2) * 64);
            sso += NT_STG_B; if (sso == 3 * NT_STG_B) sso = 0;
        }
#pragma unroll
        for (int ks = 0; ks < 4; ks++) {
            const uint32_t ko = cso + ks * 32;
            uint32_t a[2][4], b[8][2];
#pragma unroll
            for (int mt = 0; mt < 2; mt++)
                ldsm_x4(a[mt][0], a[mt][1], a[mt][2], a[mt][3],
                        aBase + ko + mt * (16 * LQH * 2));
#pragma unroll
            for (int p = 0; p < 4; p++) {
                uint32_t r0, r1, r2, r3;
                ldsm_x4(r0, r1, r2, r3, bBase + ko + p * (16 * LQH * 2));
                b[2 * p][0] = r0; b[2 * p][1] = r2;
                b[2 * p + 1][0] = r1; b[2 * p + 1][1] = r3;
            }
#pragma unroll
            for (int mt = 0; mt < 2; mt++)
#pragma unroll
                for (int nt = 0; nt < 8; nt++)
                    mma_f16(acc[mt][nt], a[mt], b[nt]);
        }
        cso += NT_STG_B; if (cso == 3 * NT_STG_B) cso = 0;
    }

    if (!isK) {
#pragma unroll
        for (int mt = 0; mt < 2; mt++)
#pragma unroll
            for (int hf = 0; hf < 2; hf++) {
                const int r = rowBase + mW + mt * 16 + rr + hf * 8;
#pragma unroll
                for (int nt = 0; nt < 8; nt++) {
                    const int c0 = colBase + nW + nt * 8 + 2 * cc;
                    float v0 = fmaxf(acc[mt][nt][hf * 2] + ev[c0], 0.f) + KEPS;
                    float v1 = fmaxf(acc[mt][nt][hf * 2 + 1] + ev[c0 + 1], 0.f) + KEPS;
                    *(half2*)(g_qph + (size_t)r * M_FEAT + c0) = __floats2half2_rn(v0, v1);
                }
            }
    } else {
        float cs[8][2];
#pragma unroll
        for (int nt = 0; nt < 8; nt++) { cs[nt][0] = 0.f; cs[nt][1] = 0.f; }
#pragma unroll
        for (int mt = 0; mt < 2; mt++)
#pragma unroll
            for (int hf = 0; hf < 2; hf++) {
                const int r = rowBase + mW + mt * 16 + rr + hf * 8;
#pragma unroll
                for (int nt = 0; nt < 8; nt++) {
                    const int c0 = colBase + nW + nt * 8 + 2 * cc;
                    float v0 = fmaxf(acc[mt][nt][hf * 2] + ev[c0], 0.f) + KEPS;
                    float v1 = fmaxf(acc[mt][nt][hf * 2 + 1] + ev[c0 + 1], 0.f) + KEPS;
                    *(half2*)(g_kph + (size_t)r * M_FEAT + c0) = __floats2half2_rn(v0, v1);
                    cs[nt][0] += v0; cs[nt][1] += v1;
                }
            }
#pragma unroll
        for (int nt = 0; nt < 8; nt++)
#pragma unroll
            for (int j = 0; j < 2; j++) {
                float s = cs[nt][j];
                s += __shfl_xor_sync(0xffffffffu, s, 4);
                s += __shfl_xor_sync(0xffffffffu, s, 8);
                s += __shfl_xor_sync(0xffffffffu, s, 16);
                cs[nt][j] = s;
            }
        if (rr == 0) {
#pragma unroll
            for (int nt = 0; nt < 8; nt++) {
                scol[wr][nW + nt * 8 + 2 * cc] = cs[nt][0];
                scol[wr][nW + nt * 8 + 2 * cc + 1] = cs[nt][1];
            }
        }
        __syncthreads();
        if (tid < 128)
            g_ks_part[rowBlock * M_FEAT + colBase + tid] =
                scol[0][tid] + scol[1][tid] + scol[2][tid] + scol[3][tid];
    }
}

// ===== kv TT fp16 body: kvT[d,m] = sum_n chih[n,d]*kph[n,m], BK=64, 3 stages =====
#define LKV 136
#define KV_STG_H (64 * LKV)
#define KV_STG_B (KV_STG_H * 2)        // 17408 B
#define KV_SMEM (3 * 2 * KV_STG_B)     // 104448 B

__device__ __forceinline__ void kv_body(char* smraw, int mBlock, int dBlock, int split) {
    __half* Asm = (__half*)smraw;
    __half* Bsm = (__half*)(smraw + 3 * KV_STG_B);

    const int tid = threadIdx.x;
    const int wid = tid >> 5, lane = tid & 31;
    const int wr = wid & 3, wc = wid >> 2;
    const int mW = wr * 32, nW = wc * 64;
    const int rowBase = dBlock * 128;
    const int colBase = mBlock * 128;
    const int kBeg = split * (N_PTS / KV_SPLIT);
    float* C = g_kvpart + (size_t)split * D_DIM * M_FEAT;

    const uint32_t aB = smem_u32(Asm), bB = smem_u32(Bsm);

    auto stage = [&](uint32_t so, int kb) {
#pragma unroll
        for (int i = 0; i < 4; i++) {
            const int c = tid + i * 256;
            const int row = c >> 4;
            const int ch = (c & 15) * 8;
            cp_async16(aB + so + (row * LKV + ch) * 2,
                       g_chih + (size_t)(kb + row) * D_DIM + rowBase + ch);
            cp_async16(bB + so + (row * LKV + ch) * 2,
                       g_kph + (size_t)(kb + row) * M_FEAT + colBase + ch);
        }
        cp_commit();
    };

    float acc[2][8][4];
#pragma unroll
    for (int mt = 0; mt < 2; mt++)
#pragma unroll
        for (int nt = 0; nt < 8; nt++)
#pragma unroll
            for (int j = 0; j < 4; j++) acc[mt][nt][j] = 0.f;

    const int nk = (N_PTS / KV_SPLIT) / 64;      // 32
    stage(0, kBeg);
    stage(KV_STG_B, kBeg + 64);
    const int rr = lane >> 2, cc = lane & 3;
    const int lrow = lane & 15, lsel = (lane >> 4) << 3;

    const uint32_t aBase = aB + (lrow * LKV + mW + lsel) * 2;
    const uint32_t bBase = bB + (lrow * LKV + nW + lsel) * 2;

    uint32_t cso = 0, sso = 2 * KV_STG_B;
    for (int kt = 0; kt < nk; kt++) {
        cp_wait<1>();
        __syncthreads();
        if (kt + 2 < nk) {
            stage(sso, kBeg + (kt + 2) * 64);
            sso += KV_STG_B; if (sso == 3 * KV_STG_B) sso = 0;
        }
#pragma unroll
        for (int ks = 0; ks < 4; ks++) {
            const uint32_t ko = cso + ks * (16 * LKV * 2);
            uint32_t a[2][4], b[8][2];
#pragma unroll
            for (int mt = 0; mt < 2; mt++) {
                uint32_t r0, r1, r2, r3;
                ldsm_x4_t(r0, r1, r2, r3, aBase + ko + mt * 32);
                a[mt][0] = r0; a[mt][1] = r2; a[mt][2] = r1; a[mt][3] = r3;
            }
#pragma unroll
            for (int p = 0; p < 4; p++) {
                uint32_t r0, r1, r2, r3;
                ldsm_x4_t(r0, r1, r2, r3, bBase + ko + p * 32);
                b[2 * p][0] = r0; b[2 * p][1] = r1;
                b[2 * p + 1][0] = r2; b[2 * p + 1][1] = r3;
            }
#pragma unroll
            for (int mt = 0; mt < 2; mt++)
#pragma unroll
                for (int nt = 0; nt < 8; nt++)
                    mma_f16(acc[mt][nt], a[mt], b[nt]);
        }
        cso += KV_STG_B; if (cso == 3 * KV_STG_B) cso = 0;
    }

#pragma unroll
    for (int mt = 0; mt < 2; mt++)
#pragma unroll
        for (int hf = 0; hf < 2; hf++) {
            const int r = rowBase + mW + mt * 16 + rr + hf * 8;
#pragma unroll
            for (int nt = 0; nt < 8; nt++) {
                const int c0 = colBase + nW + nt * 8 + 2 * cc;
                *(float2*)(C + (size_t)r * M_FEAT + c0) =
                    make_float2(acc[mt][nt][hf * 2], acc[mt][nt][hf * 2 + 1]);
            }
        }
}

// ---------------- launched kernels ----------------

// qk k-side (y<256) + chi fp16 conversion (y in [256,288), fat blocks overlapping GEMM)
__global__ void __launch_bounds__(256, 2) k_gemm_qk_k(const float* __restrict__ chi) {
    extern __shared__ __align__(16) char smraw[];
    const int y = blockIdx.y;
    if (y < 256) {
        qk_body(smraw, true, blockIdx.x, y);
    } else {
        // 128 fat cvt blocks: cb in [0,128), each converts 64 chunks of 2048 elems
        const int cb = (y - 256) * 4 + blockIdx.x;
        const int tid = threadIdx.x;
#pragma unroll 4
        for (int j = 0; j < 64; j++) {
            size_t i = ((size_t)(cb * 64 + j) * 256 + tid) * 8;
            float4 v0 = *(const float4*)(chi + i);
            float4 v1 = *(const float4*)(chi + i + 4);
            half2 h0 = __floats2half2_rn(v0.x, v0.y);
            half2 h1 = __floats2half2_rn(v0.z, v0.w);
            half2 h2 = __floats2half2_rn(v1.x, v1.y);
            half2 h3 = __floats2half2_rn(v1.z, v1.w);
            uint4 o = make_uint4(*(uint32_t*)&h0, *(uint32_t*)&h1,
                                 *(uint32_t*)&h2, *(uint32_t*)&h3);
            *(uint4*)(g_chih + i) = o;
        }
    }
}

// fused: kv blocks (y<64) + qk q-side blocks (64<=y<320) + colsum blocks (y==320)
__global__ void __launch_bounds__(256, 2) k_fused() {
    extern __shared__ __align__(16) char smraw[];
    const int y = blockIdx.y;
    if (y < 64) {
        kv_body(smraw, blockIdx.x, y >> 4, y & 15);
    } else if (y < 320) {
        qk_body(smraw, false, blockIdx.x, y - 64);
    } else {
        const int m = blockIdx.x * 128 + (threadIdx.x & 127);
        if (threadIdx.x < 128) {
            float s = 0.f;
            for (int yb = 0; yb < QK_YB; yb++) s += g_ks_part[yb * M_FEAT + m];
            g_ks[m] = s;
        }
    }
}

// num: out = (qph @ kvh^T) * 1/den, den fused
__global__ void __launch_bounds__(256, 2) k_gemm_num(float* __restrict__ out) {
    extern __shared__ __align__(16) char smraw[];
    __half* Asm = (__half*)smraw;
    __half* Bsm = (__half*)(smraw + 3 * NT_STG_B);
    __shared__ float kss[512];

    const int tid = threadIdx.x;
    const int wid = tid >> 5, lane = tid & 31;
    const int wr = wid & 3, wc = wid >> 2;
    const int mW = wr * 32, nW = wc * 64;
    const int rowBase = blockIdx.y * 128;
    const int colBase = blockIdx.x * 128;

    kss[tid] = g_ks[tid];
    kss[tid + 256] = g_ks[tid + 256];

    const uint32_t aB = smem_u32(Asm), bB = smem_u32(Bsm);

    auto stage = [&](uint32_t so, int kb) {
#pragma unroll
        for (int i = 0; i < 4; i++) {
            const int c = tid + i * 256;
            const int row = c >> 3;
            const int ch = (c & 7) * 8;
            cp_async16(aB + so + (row * LQH + ch) * 2,
                       g_qph + (size_t)(rowBase + row) * M_FEAT + kb + ch);
            cp_async16(bB + so + (row * LQH + ch) * 2,
                       g_kvh + (size_t)(colBase + row) * M_FEAT + kb + ch);
        }
        cp_commit();
    };

    float acc[2][8][4];
#pragma unroll
    for (int mt = 0; mt < 2; mt++)
#pragma unroll
        for (int nt = 0; nt < 8; nt++)
#pragma unroll
            for (int j = 0; j < 4; j++) acc[mt][nt][j] = 0.f;
    float den[2][2] = {{0.f, 0.f}, {0.f, 0.f}};

    const int nk = M_FEAT / 64;  // 8
    stage(0, 0); stage(NT_STG_B, 64);
    const int rr = lane >> 2, cc = lane & 3;
    const int lrow = lane & 15, lsel = (lane >> 4) << 3;

    const uint32_t aBase = aB + ((mW + lrow) * LQH + lsel) * 2;
    const uint32_t bBase = bB + ((nW + lrow) * LQH + lsel) * 2;

    uint32_t cso = 0, sso = 2 * NT_STG_B;
    for (int kt = 0; kt < nk; kt++) {
        cp_wait<1>();
        __syncthreads();
        if (kt + 2 < nk) {
            stage(sso, (kt + 2) * 64);
            sso += NT_STG_B; if (sso == 3 * NT_STG_B) sso = 0;
        }
#pragma unroll
        for (int ks = 0; ks < 4; ks++) {
            const uint32_t ko = cso + ks * 32;
            uint32_t a[2][4], b[8][2];
#pragma unroll
            for (int mt = 0; mt < 2; mt++)
                ldsm_x4(a[mt][0], a[mt][1], a[mt][2], a[mt][3],
                        aBase + ko + mt * (16 * LQH * 2));
#pragma unroll
            for (int p = 0; p < 4; p++) {
                uint32_t r0, r1, r2, r3;
                ldsm_x4(r0, r1, r2, r3, bBase + ko + p * (16 * LQH * 2));
                b[2 * p][0] = r0; b[2 * p][1] = r2;
                b[2 * p + 1][0] = r1; b[2 * p + 1][1] = r3;
            }
            const int kbase = kt * 64 + ks * 16;
            const float2 kA = *(const float2*)&kss[kbase + 2 * cc];
            const float2 kB = *(const float2*)&kss[kbase + 8 + 2 * cc];
#pragma unroll
            for (int mt = 0; mt < 2; mt++) {
                float2 a0 = __half22float2(*(const half2*)&a[mt][0]);
                float2 a1 = __half22float2(*(const half2*)&a[mt][1]);
                float2 a2 = __half22float2(*(const half2*)&a[mt][2]);
                float2 a3 = __half22float2(*(const half2*)&a[mt][3]);
                den[mt][0] += a0.x * kA.x + a0.y * kA.y + a2.x * kB.x + a2.y * kB.y;
                den[mt][1] += a1.x * kA.x + a1.y * kA.y + a3.x * kB.x + a3.y * kB.y;
            }
#pragma unroll
            for (int mt = 0; mt < 2; mt++)
#pragma unroll
                for (int nt = 0; nt < 8; nt++)
                    mma_f16(acc[mt][nt], a[mt], b[nt]);
        }
        cso += NT_STG_B; if (cso == 3 * NT_STG_B) cso = 0;
    }

    float inv[2][2];
#pragma unroll
    for (int mt = 0; mt < 2; mt++)
#pragma unroll
        for (int h = 0; h < 2; h++) {
            float d = den[mt][h];
            d += __shfl_xor_sync(0xffffffffu, d, 1);
            d += __shfl_xor_sync(0xffffffffu, d, 2);
            if (fabsf(d) <= NSTAB) d += 2.f * NSTAB;
            inv[mt][h] = 1.f / d;
        }

#pragma unroll
    for (int mt = 0; mt < 2; mt++)
#pragma unroll
        for (int hf = 0; hf < 2; hf++) {
            const int r = rowBase + mW + mt * 16 + rr + hf * 8;
            const float sc = inv[mt][hf];
#pragma unroll
            for (int nt = 0; nt < 8; nt++) {
                const int c0 = colBase + nW + nt * 8 + 2 * cc;
                *(float2*)(out + (size_t)r * D_DIM + c0) =
                    make_float2(acc[mt][nt][hf * 2] * sc, acc[mt][nt][hf * 2 + 1] * sc);
            }
        }
}

// ---------------- front kernel: cvt(x) + prep(Bq/Bk) + bias ----------------
// flat grid: [0,8192) cvt x ; [8192,8224) prep ; [8224,8228) bias
__global__ void __launch_bounds__(256) k_pre(const float* __restrict__ x,
                                             const float* __restrict__ Wq,
                                             const float* __restrict__ Wk,
                                             const float* __restrict__ bq,
                                             const float* __restrict__ bk,
                                             const float* __restrict__ proj) {
    const int bid = blockIdx.x;
    const int tid = threadIdx.x;

    if (bid < 8192) {                         // cvt x
        size_t i = ((size_t)bid * 256 + tid) * 8;
        float4 v0 = *(const float4*)(x + i);
        float4 v1 = *(const float4*)(x + i + 4);
        half2 h0 = __floats2half2_rn(v0.x, v0.y);
        half2 h1 = __floats2half2_rn(v0.z, v0.w);
        half2 h2 = __floats2half2_rn(v1.x, v1.y);
        half2 h3 = __floats2half2_rn(v1.z, v1.w);
        uint4 o = make_uint4(*(uint32_t*)&h0, *(uint32_t*)&h1, *(uint32_t*)&h2, *(uint32_t*)&h3);
        *(uint4*)(g_xh + i) = o;
    } else if (bid < 8224) {                  // prep: Bq/Bk = proj @ W^T -> fp16
        const int pb = bid - 8192;
        const int zb = pb >> 4;
        const int xb = pb & 3, yb = (pb >> 2) & 3;
        const float* B = zb ? Wk : Wq;
        __half* C = zb ? g_Bkh : g_Bqh;
        __shared__ float As[8][128];
        __shared__ float Bs[8][128];
        const int tx = tid & 15, ty = tid >> 4;
        const int rowBase = yb * 128, colBase = xb * 128;
        const int rA = tid >> 1, cA = (tid & 1) * 4;

        float acc[8][8];
#pragma unroll
        for (int i = 0; i < 8; i++)
#pragma unroll
            for (int j = 0; j < 8; j++) acc[i][j] = 0.f;

        for (int kb = 0; kb < D_DIM; kb += 8) {
            float4 av = *(const float4*)(proj + (rowBase + rA) * D_DIM + kb + cA);
            float4 bv = *(const float4*)(B + (colBase + rA) * D_DIM + kb + cA);
            __syncthreads();
            As[cA + 0][rA] = av.x; As[cA + 1][rA] = av.y; As[cA + 2][rA] = av.z; As[cA + 3][rA] = av.w;
            Bs[cA + 0][rA] = bv.x; Bs[cA + 1][rA] = bv.y; Bs[cA + 2][rA] = bv.z; Bs[cA + 3][rA] = bv.w;
            __syncthreads();
#pragma unroll
            for (int k = 0; k < 8; k++) {
                float a[8], b[8];
#pragma unroll
                for (int i = 0; i < 8; i++) a[i] = As[k][ty * 8 + i];
#pragma unroll
                for (int j = 0; j < 8; j++) b[j] = Bs[k][tx * 8 + j];
#pragma unroll
                for (int i = 0; i < 8; i++)
#pragma unroll
                    for (int j = 0; j < 8; j++) acc[i][j] = fmaf(a[i], b[j], acc[i][j]);
            }
        }
#pragma unroll
        for (int i = 0; i < 8; i++) {
            __half* cp = C + (rowBase + ty * 8 + i) * D_DIM + colBase + tx * 8;
#pragma unroll
            for (int j = 0; j < 8; j++) cp[j] = __float2half_rn(acc[i][j]);
        }
    } else {                                  // bias
        const int b2 = bid - 8224;
        const int xb = b2 & 1, yb = b2 >> 1;
        const int m = xb * 256 + tid;
        const float* b = yb ? bk : bq;
        float* c = yb ? g_ck : g_cq;
        float s = 0.f;
        for (int j = 0; j < D_DIM; j++) s += b[j] * proj[m * D_DIM + j];
        c[m] = s;
    }
}

__global__ void k_kvred() {
    int i = blockIdx.x * blockDim.x + threadIdx.x;
    float s = 0.f;
#pragma unroll
    for (int z = 0; z < KV_SPLIT; z++) s += g_kvpart[(size_t)z * D_DIM * M_FEAT + i];
    g_kvh[i] = __float2half_rn(s);
}

// ---------------- launch ----------------
extern "C" void kernel_launch(void* const* d_in, const int* in_sizes, int n_in,
                              void* d_out, int out_size) {
    const float* chi  = (const float*)d_in[0];
    const float* x    = (const float*)d_in[1];
    const float* Wq   = (const float*)d_in[2];
    const float* bq   = (const float*)d_in[3];
    const float* Wk   = (const float*)d_in[4];
    const float* bk   = (const float*)d_in[5];
    const float* proj = (const float*)d_in[6];
    float* out = (float*)d_out;

    cudaFuncSetAttribute(k_gemm_qk_k, cudaFuncAttributeMaxDynamicSharedMemorySize, NT_SMEM);
    cudaFuncSetAttribute(k_fused,     cudaFuncAttributeMaxDynamicSharedMemorySize, NT_SMEM);
    cudaFuncSetAttribute(k_gemm_num,  cudaFuncAttributeMaxDynamicSharedMemorySize, NT_SMEM);

    // 1) front: cvt x + prep Bq/Bk + bias (chi cvt moved into launch 2)
    k_pre<<<8228, 256>>>(x, Wq, Wk, bq, bk, proj);
    // 2) k' GEMM (+ colsum partials) with chi-cvt blocks overlapped (y>=256)
    k_gemm_qk_k<<<dim3(4, 288), 256, NT_SMEM>>>(chi);
    // 3) fused: kv GEMM (y<64) + q' GEMM (64<=y<320) + colsum finalize (y==320)
    k_fused<<<dim3(4, 321), 256, NT_SMEM>>>();
    // 4) kv partial reduce -> fp16
    k_kvred<<<(D_DIM * M_FEAT) / 256, 256>>>();
    // 5) out = (q' @ kvT^T) * 1/den
    k_gemm_num<<<dim3(D_DIM / 128, N_PTS / 128), 256, NT_SMEM>>>(out);
}